// round 10
// baseline (speedup 1.0000x reference)
#include <cuda_runtime.h>
#include <cuda_fp16.h>
#include <cstdint>

#define S_LEN  512
#define BATCH  64
#define HID    1024
#define LAYERS 3
#define BH     (BATCH*HID)     // 65536
#define KCH    64              // K per chunk
#define CHUNKS 16              // 1024/64
#define DEPTH  3               // cp.async ring depth

#define SR     72              // smem row stride in halfs (144B)
// slot rows: [0,64) A_hi, [64,128) A_lo, [128,256) W_hi, [256,384) W_lo
#define SLOT_HALFS (384*SR)            // 27648
#define SLOT_BYTES (SLOT_HALFS*2)      // 55296
#define SMEM_REQ (1024 + DEPTH*SLOT_BYTES)   // 166912 B

#define WBLK   (128*1024)      // one weight block: 128 rows x K=1024
#define LO_SCALE    2048.f
#define INV_LOSCALE (1.f/2048.f)

typedef __half h16;

// ---------------- device scratch (no runtime allocation) -------------------
__device__ h16 g_xhi[(size_t)S_LEN*BH];
__device__ h16 g_xlo[(size_t)S_LEN*BH];
__device__ h16 g_wBhi[(size_t)LAYERS*2*3*8*WBLK];
__device__ h16 g_wBlo[(size_t)LAYERS*2*3*8*WBLK];
__device__ float g_h  [LAYERS*2*BH];            // h state, parity double buffer
__device__ h16   g_hhi[LAYERS*2*BH];
__device__ h16   g_hlo[LAYERS*2*BH];
__device__ float g_gates[(size_t)2*LAYERS*6*BH]; // parity-double-buffered
__device__ int   g_flag[LAYERS*8];               // group rendezvous (l,ub)
__device__ int   g_lflag[LAYERS];                // per-layer completed-CTA count

// ---------------- helpers ----------------------------------------------------
__device__ __forceinline__ void ldsm4(uint32_t r[4], const h16* p) {
    uint32_t a = (uint32_t)__cvta_generic_to_shared(p);
    asm volatile("ldmatrix.sync.aligned.m8n8.x4.shared.b16 {%0,%1,%2,%3}, [%4];"
                 : "=r"(r[0]), "=r"(r[1]), "=r"(r[2]), "=r"(r[3]) : "r"(a));
}

// main product: f16 inputs, f32 accumulate
__device__ __forceinline__ void mma_f32acc(float c[4], const uint32_t a[4],
                                           uint32_t b0, uint32_t b1) {
    asm volatile("mma.sync.aligned.m16n8k16.row.col.f32.f16.f16.f32 "
                 "{%0,%1,%2,%3}, {%4,%5,%6,%7}, {%8,%9}, {%0,%1,%2,%3};"
                 : "+f"(c[0]), "+f"(c[1]), "+f"(c[2]), "+f"(c[3])
                 : "r"(a[0]), "r"(a[1]), "r"(a[2]), "r"(a[3]), "r"(b0), "r"(b1));
}

// cross products: f16 inputs, f16 accumulate (2 regs = 4 packed halfs)
__device__ __forceinline__ void mma_f16acc(uint32_t c[2], const uint32_t a[4],
                                           uint32_t b0, uint32_t b1) {
    asm volatile("mma.sync.aligned.m16n8k16.row.col.f16.f16.f16.f16 "
                 "{%0,%1}, {%2,%3,%4,%5}, {%6,%7}, {%0,%1};"
                 : "+r"(c[0]), "+r"(c[1])
                 : "r"(a[0]), "r"(a[1]), "r"(a[2]), "r"(a[3]), "r"(b0), "r"(b1));
}

// f16 digit split: hi = f16(v); lo = f16((v - hi) * 2048)
__device__ __forceinline__ void split2(float v, h16& hi, h16& lo) {
    hi = __float2half_rn(v);
    lo = __float2half_rn((v - __half2float(hi)) * LO_SCALE);
}

__device__ __forceinline__ void cp16(h16* dst, const h16* src) {
    uint32_t d = (uint32_t)__cvta_generic_to_shared(dst);
    asm volatile("cp.async.cg.shared.global [%0], [%1], 16;" :: "r"(d), "l"(src));
}

__device__ __forceinline__ int ldacq(const int* p) {
    int v;
    asm volatile("ld.acquire.gpu.s32 %0, [%1];" : "=r"(v) : "l"(p) : "memory");
    return v;
}

__device__ __forceinline__ void spin_ge(const int* p, int target) {
    while (ldacq(p) < target) __nanosleep(64);
}

// ---------------- prep kernels ----------------------------------------------
__global__ void permute_weights_kernel(const float* __restrict__ wih,
                                       const float* __restrict__ whh) {
    size_t i = (size_t)blockIdx.x * blockDim.x + threadIdx.x;
    if (i >= (size_t)LAYERS * 3 * HID * HID) return;
    int k = (int)(i % HID);
    size_t row = i / HID;
    int l = (int)(row / (3 * HID));
    int r = (int)(row % (3 * HID));
    int g = r >> 10, u = r & 1023;
    int ub = u >> 7, rr = u & 127;
    size_t dih = ((size_t)(((l * 2 + 0) * 3 + g) * 8 + ub)) * WBLK + (size_t)rr * 1024 + k;
    size_t dhh = ((size_t)(((l * 2 + 1) * 3 + g) * 8 + ub)) * WBLK + (size_t)rr * 1024 + k;
    h16 hi, lo;
    split2(wih[i], hi, lo); g_wBhi[dih] = hi; g_wBlo[dih] = lo;
    split2(whh[i], hi, lo); g_wBhi[dhh] = hi; g_wBlo[dhh] = lo;
}

__global__ void split_x_kernel(const float* __restrict__ x) {
    size_t i = (size_t)blockIdx.x * blockDim.x + threadIdx.x;
    if (i >= (size_t)S_LEN * BH) return;
    h16 hi, lo;
    split2(x[i], hi, lo); g_xhi[i] = hi; g_xlo[i] = lo;
}

__global__ void init_h_kernel(const float* __restrict__ h0) {
    if (blockIdx.x == 0 && threadIdx.x < LAYERS * 8) {
        g_flag[threadIdx.x] = 0;
        if (threadIdx.x < LAYERS) g_lflag[threadIdx.x] = 0;
    }
    size_t i = (size_t)blockIdx.x * blockDim.x + threadIdx.x;
    if (i >= (size_t)LAYERS * BH) return;
    int l = (int)(i / BH);
    size_t j = i % BH;
    float v = h0[i];
    size_t dst = ((size_t)l * 2 + 0) * BH + j;
    g_h[dst] = v;
    h16 hi, lo;
    split2(v, hi, lo); g_hhi[dst] = hi; g_hlo[dst] = lo;
}

// ---------------- chunk loaders ---------------------------------------------
__device__ __forceinline__ void load_chunk_A(
    h16* slot, int kb,
    const h16* __restrict__ Ahi, const h16* __restrict__ Alo, int tid)
{
#pragma unroll
    for (int i = tid; i < 1024; i += 512) {
        int row = i >> 3, c16 = i & 7;
        int pl = row >> 6, r = row & 63;
        const h16* src = (pl ? Alo : Ahi) + (size_t)r * 1024 + kb + c16 * 8;
        cp16(slot + row * SR + c16 * 8, src);
    }
}

__device__ __forceinline__ void load_chunk_W(
    h16* slot, int kb,
    const h16* __restrict__ Whi, const h16* __restrict__ Wlo, int tid)
{
#pragma unroll
    for (int i = tid; i < 2048; i += 512) {
        int row = i >> 3, c16 = i & 7;
        int pl = row >> 7, r = row & 127;
        const h16* src = (pl ? Wlo : Whi) + (size_t)r * 1024 + kb + c16 * 8;
        cp16(slot + (128 + row) * SR + c16 * 8, src);
    }
}

// ---------------- persistent GRU kernel --------------------------------------
// grid (48, 3): l = blockIdx.y; q: p=q/24, g=(q%24)/8, ub=q%8. Each CTA loops
// t = 0..511 in its fixed role, synchronized by acquire/release flags.
// Cross-step prefetch: W chunks 0-1 (and x-A for l0/p0) are issued during the
// PREVIOUS step's epilogue; p=0 CTAs use a relaxed (WAR-only) start barrier.
__global__ __launch_bounds__(512) void gru_persistent_kernel(
    const float* __restrict__ bih, const float* __restrict__ bhh,
    float* __restrict__ out)
{
    const int l  = blockIdx.y;
    const int q  = blockIdx.x;
    const int p  = q / 24;
    const int g  = (q % 24) / 8;
    const int ub = q & 7;
    const int u0 = ub * 128;

    const int tid  = threadIdx.x;
    const int lane = tid & 31;
    const int wid  = tid >> 5;
    const int wm   = wid >> 2;
    const int wn   = wid & 3;

    extern __shared__ __align__(16) unsigned char smem_raw[];
    uint32_t dyn_u = (uint32_t)__cvta_generic_to_shared(smem_raw);
    uint32_t s0u   = (dyn_u + 1023u) & ~1023u;
    h16* sbase = (h16*)(smem_raw + (s0u - dyn_u));

    size_t wb = (size_t)(((l * 2 + p) * 3 + g) * 8 + ub) * WBLK;
    const h16* Whi = g_wBhi + wb;
    const h16* Wlo = g_wBlo + wb;

    const bool xstatic = (l == 0 && p == 0);   // A source is static x

    const int rowA  = wm * 16 + (lane & 15);
    const int ahalf = (lane >> 4) * 8;
    const int rowB  = (lane & 7) + ((lane & 16) ? 8 : 0);
    const int bhalf = (lane & 8) ? 8 : 0;

    const int lG = l * 3 * HID;
    const float* bihp = bih + lG;
    const float* bhhp = bhh + lG;
    const int sl    = p * 3 + g;
    const int start = sl * 1366;
    const int end   = (start + 1366 < 8192) ? start + 1366 : 8192;

    // ---- pre-loop: prefetch step-0 W chunks 0,1 (+A for static-x CTAs) ----
    load_chunk_W(sbase, 0, Whi, Wlo, tid);
    load_chunk_W(sbase + SLOT_HALFS, KCH, Whi, Wlo, tid);
    if (xstatic) {
        load_chunk_A(sbase, 0, g_xhi, g_xlo, tid);
        load_chunk_A(sbase + SLOT_HALFS, KCH, g_xhi, g_xlo, tid);
    }

    for (int t = 0; t < S_LEN; ++t) {
        const int par = t & 1;

        const h16 *Ahi, *Alo;
        if (p == 0) {
            if (l == 0) { Ahi = g_xhi + (size_t)t * BH;  Alo = g_xlo + (size_t)t * BH; }
            else {
                size_t o = ((size_t)(l - 1) * 2 + (par ^ 1)) * BH;   // h_{l-1}[t]
                Ahi = g_hhi + o;  Alo = g_hlo + o;
            }
        } else {
            size_t o = ((size_t)l * 2 + par) * BH;                    // h_l[t-1]
            Ahi = g_hhi + o;  Alo = g_hlo + o;
        }

        float acc[4][4];          // main product, f32
        uint32_t cacc[4][2];      // cross products, packed f16 (scaled by 2048)
#pragma unroll
        for (int j = 0; j < 4; ++j) {
#pragma unroll
            for (int c = 0; c < 4; ++c) acc[j][c] = 0.f;
            cacc[j][0] = 0u; cacc[j][1] = 0u;
        }

        // ---- start-of-step barriers (prefetched W/A streams during spin) ----
        if (tid == 0) {
            if (p == 1)      spin_ge(&g_lflag[l], 48 * t);          // data: h_l[t-1]
            else if (t >= 1) spin_ge(&g_lflag[l], 48 * (t - 1));    // WAR only
            if (p == 0 && l > 0)            spin_ge(&g_lflag[l - 1], 48 * (t + 1));
            if (l < LAYERS - 1 && t >= 1)   spin_ge(&g_lflag[l + 1], 48 * (t - 1));
        }
        __syncthreads();

        if (!xstatic) {
            load_chunk_A(sbase, 0, Ahi, Alo, tid);
            asm volatile("cp.async.commit_group;" ::: "memory");   // G1={W0,W1,A0}
            load_chunk_A(sbase + SLOT_HALFS, KCH, Ahi, Alo, tid);
            asm volatile("cp.async.commit_group;" ::: "memory");   // G2={A1}
        } else {
            asm volatile("cp.async.commit_group;" ::: "memory");   // G1={W0,W1,A0,A1}
            asm volatile("cp.async.commit_group;" ::: "memory");   // G2={}
        }

        // ---- main loop: 16 chunks, depth-3 ring ----
        for (int c = 0; c < CHUNKS; ++c) {
            asm volatile("cp.async.wait_group 1;" ::: "memory");
            __syncthreads();
            const int nc = c + 2;
            if (nc < CHUNKS) {
                h16* nslot = sbase + (size_t)(nc % DEPTH) * SLOT_HALFS;
                load_chunk_W(nslot, nc * KCH, Whi, Wlo, tid);
                load_chunk_A(nslot, nc * KCH, Ahi, Alo, tid);
            }
            asm volatile("cp.async.commit_group;" ::: "memory");   // drain-safe

            const h16* slot = sbase + (size_t)(c % DEPTH) * SLOT_HALFS;
#pragma unroll
            for (int ks = 0; ks < 4; ++ks) {
                uint32_t ah[4], al[4];
                ldsm4(ah, slot + rowA * SR + ks * 16 + ahalf);
                ldsm4(al, slot + (64 + rowA) * SR + ks * 16 + ahalf);
#pragma unroll
                for (int np = 0; np < 2; ++np) {
                    uint32_t bh[4], bl[4];
                    int wr = 128 + wn * 32 + np * 16 + rowB;
                    ldsm4(bh, slot + wr * SR + ks * 16 + bhalf);
                    ldsm4(bl, slot + (wr + 128) * SR + ks * 16 + bhalf);
                    int f = np * 2;
                    mma_f32acc(acc[f],     ah, bh[0], bh[1]);
                    mma_f32acc(acc[f + 1], ah, bh[2], bh[3]);
                    mma_f16acc(cacc[f],     al, bh[0], bh[1]);
                    mma_f16acc(cacc[f + 1], al, bh[2], bh[3]);
                    mma_f16acc(cacc[f],     ah, bl[0], bl[1]);
                    mma_f16acc(cacc[f + 1], ah, bl[2], bl[3]);
                }
            }
        }
        __syncthreads();   // all warps done reading slots 0/1 (only empty groups pend)

        // ---- cross-step prefetch: next step's W (and static-x A) chunks 0,1 ----
        if (t + 1 < S_LEN) {
            load_chunk_W(sbase, 0, Whi, Wlo, tid);
            load_chunk_W(sbase + SLOT_HALFS, KCH, Whi, Wlo, tid);
            if (xstatic) {
                const h16* nAhi = g_xhi + (size_t)(t + 1) * BH;
                const h16* nAlo = g_xlo + (size_t)(t + 1) * BH;
                load_chunk_A(sbase, 0, nAhi, nAlo, tid);
                load_chunk_A(sbase + SLOT_HALFS, KCH, nAhi, nAlo, tid);
            }
        }

        // ---- fold cross terms into main acc ----
#pragma unroll
        for (int f = 0; f < 4; ++f) {
            float2 c0 = __half22float2(*(const __half2*)&cacc[f][0]);
            float2 c1 = __half22float2(*(const __half2*)&cacc[f][1]);
            acc[f][0] += c0.x * INV_LOSCALE;
            acc[f][1] += c0.y * INV_LOSCALE;
            acc[f][2] += c1.x * INV_LOSCALE;
            acc[f][3] += c1.y * INV_LOSCALE;
        }

        // ---- store gate tile to global (parity-double-buffered) ----
        float* plane = g_gates + ((size_t)par * LAYERS * 6 + l * 6 + sl) * BH;
        {
            int gr = lane >> 2, t4 = lane & 3;
#pragma unroll
            for (int f = 0; f < 4; ++f) {
                int u = u0 + wn * 32 + f * 8 + t4 * 2;
                int r0 = wm * 16 + gr;
                *(float2*)(plane + (size_t)r0 * 1024 + u)       = make_float2(acc[f][0], acc[f][1]);
                *(float2*)(plane + (size_t)(r0 + 8) * 1024 + u) = make_float2(acc[f][2], acc[f][3]);
            }
        }

        // ---- group rendezvous: 6 CTAs of (l, ub) ----
        __syncthreads();
        if (tid == 0) {
            __threadfence();
            atomicAdd(&g_flag[l * 8 + ub], 1);
            spin_ge(&g_flag[l * 8 + ub], 6 * (t + 1));
        }
        __syncthreads();

        // ---- distributed pointwise GRU (slice sl of this ub's 8192 elems) ----
        const float* hsrc = g_h + ((size_t)l * 2 + par) * BH;
        float*       hdst = g_h + ((size_t)l * 2 + (par ^ 1)) * BH;
        h16* hhid = g_hhi + ((size_t)l * 2 + (par ^ 1)) * BH;
        h16* hlod = g_hlo + ((size_t)l * 2 + (par ^ 1)) * BH;
        const float* GI = g_gates + ((size_t)par * LAYERS * 6 + l * 6) * BH;
        const float* GH = GI + 3 * (size_t)BH;

        for (int e = start + tid; e < end; e += 512) {
            int b  = e >> 7;
            int u  = u0 + (e & 127);
            size_t ix = (size_t)b * 1024 + u;
            float gi_r = __ldcg(GI + ix),                  gh_r = __ldcg(GH + ix);
            float gi_z = __ldcg(GI + BH + ix),             gh_z = __ldcg(GH + BH + ix);
            float gi_n = __ldcg(GI + 2 * (size_t)BH + ix), gh_n = __ldcg(GH + 2 * (size_t)BH + ix);
            float pr = gi_r + bihp[u]           + gh_r + bhhp[u];
            float pz = gi_z + bihp[HID + u]     + gh_z + bhhp[HID + u];
            float rg = 1.f / (1.f + __expf(-pr));
            float zg = 1.f / (1.f + __expf(-pz));
            float nn = tanhf(gi_n + bihp[2 * HID + u] + rg * (gh_n + bhhp[2 * HID + u]));
            float hold = hsrc[ix];
            float hn = (1.f - zg) * nn + zg * hold;
            hdst[ix] = hn;
            h16 hi, lo;
            split2(hn, hi, lo);
            hhid[ix] = hi;
            hlod[ix] = lo;
            if (l == LAYERS - 1)
                out[(size_t)t * BH + ix] = hn;
        }

        // ---- release: this CTA completed step t ----
        __syncthreads();
        if (tid == 0) {
            __threadfence();
            atomicAdd(&g_lflag[l], 1);
        }
    }
}

// ---------------- launch -----------------------------------------------------
extern "C" void kernel_launch(void* const* d_in, const int* in_sizes, int n_in,
                              void* d_out, int out_size)
{
    const float* x   = (const float*)d_in[0];
    const float* h0  = (const float*)d_in[1];
    const float* wih = (const float*)d_in[2];
    const float* whh = (const float*)d_in[3];
    const float* bih = (const float*)d_in[4];
    const float* bhh = (const float*)d_in[5];
    float* out = (float*)d_out;

    cudaFuncSetAttribute(gru_persistent_kernel,
                         cudaFuncAttributeMaxDynamicSharedMemorySize, SMEM_REQ);

    {
        size_t n = (size_t)LAYERS * 3 * HID * HID;
        permute_weights_kernel<<<(unsigned)((n + 255) / 256), 256>>>(wih, whh);
    }
    {
        size_t n = (size_t)S_LEN * BH;
        split_x_kernel<<<(unsigned)((n + 255) / 256), 256>>>(x);
    }
    {
        size_t n = (size_t)LAYERS * BH;
        init_h_kernel<<<(unsigned)((n + 255) / 256), 256>>>(h0);  // + flag reset
    }
    gru_persistent_kernel<<<dim3(48, 3), 512, SMEM_REQ>>>(bih, bhh, out);
}

// round 11
// speedup vs baseline: 1.5808x; 1.5808x over previous
#include <cuda_runtime.h>
#include <cuda_fp16.h>
#include <cstdint>

#define S_LEN  512
#define BATCH  64
#define HID    1024
#define LAYERS 3
#define BH     (BATCH*HID)     // 65536
#define KCH    64              // K per chunk
#define CHUNKS 16              // 1024/64
#define DEPTH  3               // cp.async ring depth

#define SR     72              // smem row stride in halfs (144B)
// slot rows: [0,64) A_hi, [64,128) A_lo, [128,256) W_hi, [256,384) W_lo
#define SLOT_HALFS (384*SR)            // 27648
#define SLOT_BYTES (SLOT_HALFS*2)      // 55296
#define SMEM_REQ (1024 + DEPTH*SLOT_BYTES)   // 166912 B

#define WBLK   (128*1024)      // one weight block: 128 rows x K=1024
#define LO_SCALE    2048.f
#define INV_LOSCALE (1.f/2048.f)

typedef __half h16;

// ---------------- device scratch (no runtime allocation) -------------------
__device__ h16 g_xhi[(size_t)S_LEN*BH];
__device__ h16 g_xlo[(size_t)S_LEN*BH];
__device__ h16 g_wBhi[(size_t)LAYERS*2*3*8*WBLK];
__device__ h16 g_wBlo[(size_t)LAYERS*2*3*8*WBLK];
__device__ float g_h  [LAYERS*2*BH];            // h state, parity double buffer
__device__ h16   g_hhi[LAYERS*2*BH];
__device__ h16   g_hlo[LAYERS*2*BH];
__device__ float g_gates[(size_t)2*LAYERS*6*BH]; // parity-double-buffered
__device__ int   g_flag[LAYERS*8];               // group rendezvous (l,ub)
__device__ int   g_lflag[LAYERS];                // per-layer completed-CTA count

// ---------------- helpers ----------------------------------------------------
__device__ __forceinline__ void ldsm4(uint32_t r[4], const h16* p) {
    uint32_t a = (uint32_t)__cvta_generic_to_shared(p);
    asm volatile("ldmatrix.sync.aligned.m8n8.x4.shared.b16 {%0,%1,%2,%3}, [%4];"
                 : "=r"(r[0]), "=r"(r[1]), "=r"(r[2]), "=r"(r[3]) : "r"(a));
}

// main product: f16 inputs, f32 accumulate
__device__ __forceinline__ void mma_f32acc(float c[4], const uint32_t a[4],
                                           uint32_t b0, uint32_t b1) {
    asm volatile("mma.sync.aligned.m16n8k16.row.col.f32.f16.f16.f32 "
                 "{%0,%1,%2,%3}, {%4,%5,%6,%7}, {%8,%9}, {%0,%1,%2,%3};"
                 : "+f"(c[0]), "+f"(c[1]), "+f"(c[2]), "+f"(c[3])
                 : "r"(a[0]), "r"(a[1]), "r"(a[2]), "r"(a[3]), "r"(b0), "r"(b1));
}

// cross products: f16 inputs, f16 accumulate (2 regs = 4 packed halfs)
__device__ __forceinline__ void mma_f16acc(uint32_t c[2], const uint32_t a[4],
                                           uint32_t b0, uint32_t b1) {
    asm volatile("mma.sync.aligned.m16n8k16.row.col.f16.f16.f16.f16 "
                 "{%0,%1}, {%2,%3,%4,%5}, {%6,%7}, {%0,%1};"
                 : "+r"(c[0]), "+r"(c[1])
                 : "r"(a[0]), "r"(a[1]), "r"(a[2]), "r"(a[3]), "r"(b0), "r"(b1));
}

// f16 digit split: hi = f16(v); lo = f16((v - hi) * 2048)
__device__ __forceinline__ void split2(float v, h16& hi, h16& lo) {
    hi = __float2half_rn(v);
    lo = __float2half_rn((v - __half2float(hi)) * LO_SCALE);
}

__device__ __forceinline__ void cp16(h16* dst, const h16* src) {
    uint32_t d = (uint32_t)__cvta_generic_to_shared(dst);
    asm volatile("cp.async.cg.shared.global [%0], [%1], 16;" :: "r"(d), "l"(src));
}

__device__ __forceinline__ int ldacq(const int* p) {
    int v;
    asm volatile("ld.acquire.gpu.s32 %0, [%1];" : "=r"(v) : "l"(p) : "memory");
    return v;
}

__device__ __forceinline__ void spin_ge(const int* p, int target) {
    while (ldacq(p) < target) __nanosleep(64);
}

// ---------------- prep kernels ----------------------------------------------
__global__ void permute_weights_kernel(const float* __restrict__ wih,
                                       const float* __restrict__ whh) {
    size_t i = (size_t)blockIdx.x * blockDim.x + threadIdx.x;
    if (i >= (size_t)LAYERS * 3 * HID * HID) return;
    int k = (int)(i % HID);
    size_t row = i / HID;
    int l = (int)(row / (3 * HID));
    int r = (int)(row % (3 * HID));
    int g = r >> 10, u = r & 1023;
    int ub = u >> 7, rr = u & 127;
    size_t dih = ((size_t)(((l * 2 + 0) * 3 + g) * 8 + ub)) * WBLK + (size_t)rr * 1024 + k;
    size_t dhh = ((size_t)(((l * 2 + 1) * 3 + g) * 8 + ub)) * WBLK + (size_t)rr * 1024 + k;
    h16 hi, lo;
    split2(wih[i], hi, lo); g_wBhi[dih] = hi; g_wBlo[dih] = lo;
    split2(whh[i], hi, lo); g_wBhi[dhh] = hi; g_wBlo[dhh] = lo;
}

__global__ void split_x_kernel(const float* __restrict__ x) {
    size_t i = (size_t)blockIdx.x * blockDim.x + threadIdx.x;
    if (i >= (size_t)S_LEN * BH) return;
    h16 hi, lo;
    split2(x[i], hi, lo); g_xhi[i] = hi; g_xlo[i] = lo;
}

__global__ void init_h_kernel(const float* __restrict__ h0) {
    if (blockIdx.x == 0 && threadIdx.x < LAYERS * 8) {
        g_flag[threadIdx.x] = 0;
        if (threadIdx.x < LAYERS) g_lflag[threadIdx.x] = 0;
    }
    size_t i = (size_t)blockIdx.x * blockDim.x + threadIdx.x;
    if (i >= (size_t)LAYERS * BH) return;
    int l = (int)(i / BH);
    size_t j = i % BH;
    float v = h0[i];
    size_t dst = ((size_t)l * 2 + 0) * BH + j;
    g_h[dst] = v;
    h16 hi, lo;
    split2(v, hi, lo); g_hhi[dst] = hi; g_hlo[dst] = lo;
}

// ---------------- chunk loaders ---------------------------------------------
__device__ __forceinline__ void load_chunk_A(
    h16* slot, int kb,
    const h16* __restrict__ Ahi, const h16* __restrict__ Alo, int tid)
{
#pragma unroll
    for (int i = tid; i < 1024; i += 512) {
        int row = i >> 3, c16 = i & 7;
        int pl = row >> 6, r = row & 63;
        const h16* src = (pl ? Alo : Ahi) + (size_t)r * 1024 + kb + c16 * 8;
        cp16(slot + row * SR + c16 * 8, src);
    }
}

__device__ __forceinline__ void load_chunk_W(
    h16* slot, int kb,
    const h16* __restrict__ Whi, const h16* __restrict__ Wlo, int tid)
{
#pragma unroll
    for (int i = tid; i < 2048; i += 512) {
        int row = i >> 3, c16 = i & 7;
        int pl = row >> 7, r = row & 127;
        const h16* src = (pl ? Wlo : Whi) + (size_t)r * 1024 + kb + c16 * 8;
        cp16(slot + (128 + row) * SR + c16 * 8, src);
    }
}

// ---------------- persistent GRU kernel --------------------------------------
// grid (48, 3): l = blockIdx.y; q: p=q/24, g=(q%24)/8, ub=q%8. Each CTA loops
// t = 0..511 in its fixed role, synchronized by acquire/release flags.
// R9 structure (best known); start-of-step spins parallelized across warps.
__global__ __launch_bounds__(512) void gru_persistent_kernel(
    const float* __restrict__ bih, const float* __restrict__ bhh,
    float* __restrict__ out)
{
    const int l  = blockIdx.y;
    const int q  = blockIdx.x;
    const int p  = q / 24;
    const int g  = (q % 24) / 8;
    const int ub = q & 7;
    const int u0 = ub * 128;

    const int tid  = threadIdx.x;
    const int lane = tid & 31;
    const int wid  = tid >> 5;
    const int wm   = wid >> 2;
    const int wn   = wid & 3;

    extern __shared__ __align__(16) unsigned char smem_raw[];
    uint32_t dyn_u = (uint32_t)__cvta_generic_to_shared(smem_raw);
    uint32_t s0u   = (dyn_u + 1023u) & ~1023u;
    h16* sbase = (h16*)(smem_raw + (s0u - dyn_u));

    size_t wb = (size_t)(((l * 2 + p) * 3 + g) * 8 + ub) * WBLK;
    const h16* Whi = g_wBhi + wb;
    const h16* Wlo = g_wBlo + wb;

    const int rowA  = wm * 16 + (lane & 15);
    const int ahalf = (lane >> 4) * 8;
    const int rowB  = (lane & 7) + ((lane & 16) ? 8 : 0);
    const int bhalf = (lane & 8) ? 8 : 0;

    const int lG = l * 3 * HID;
    const float* bihp = bih + lG;
    const float* bhhp = bhh + lG;
    const int sl    = p * 3 + g;
    const int start = sl * 1366;
    const int end   = (start + 1366 < 8192) ? start + 1366 : 8192;

    for (int t = 0; t < S_LEN; ++t) {
        const int par = t & 1;

        const h16 *Ahi, *Alo;
        if (p == 0) {
            if (l == 0) { Ahi = g_xhi + (size_t)t * BH;  Alo = g_xlo + (size_t)t * BH; }
            else {
                size_t o = ((size_t)(l - 1) * 2 + (par ^ 1)) * BH;   // h_{l-1}[t]
                Ahi = g_hhi + o;  Alo = g_hlo + o;
            }
        } else {
            size_t o = ((size_t)l * 2 + par) * BH;                    // h_l[t-1]
            Ahi = g_hhi + o;  Alo = g_hlo + o;
        }

        float acc[4][4];          // main product, f32
        uint32_t cacc[4][2];      // cross products, packed f16 (scaled by 2048)
#pragma unroll
        for (int j = 0; j < 4; ++j) {
#pragma unroll
            for (int c = 0; c < 4; ++c) acc[j][c] = 0.f;
            cacc[j][0] = 0u; cacc[j][1] = 0u;
        }

        // ---- W of chunk 0 (no cross-step dependency) hides the flag spins ----
        // Spins parallelized: one warp-leader per flag, max() instead of sum().
        load_chunk_W(sbase, 0, Whi, Wlo, tid);
        if (tid == 0) {
            spin_ge(&g_lflag[l], 48 * t);                       // own layer t-1 done
        } else if (tid == 32) {
            if (p == 0 && l > 0) spin_ge(&g_lflag[l - 1], 48 * (t + 1));
        } else if (tid == 64) {
            if (l < LAYERS - 1 && t >= 1) spin_ge(&g_lflag[l + 1], 48 * (t - 1));
        }
        __syncthreads();
        load_chunk_A(sbase, 0, Ahi, Alo, tid);
        asm volatile("cp.async.commit_group;" ::: "memory");
        load_chunk_W(sbase + SLOT_HALFS, KCH, Whi, Wlo, tid);
        load_chunk_A(sbase + SLOT_HALFS, KCH, Ahi, Alo, tid);
        asm volatile("cp.async.commit_group;" ::: "memory");

        // ---- main loop: 16 chunks, depth-3 ring ----
        for (int c = 0; c < CHUNKS; ++c) {
            asm volatile("cp.async.wait_group 1;" ::: "memory");
            __syncthreads();
            const int nc = c + DEPTH - 1;
            if (nc < CHUNKS) {
                h16* nslot = sbase + (size_t)(nc % DEPTH) * SLOT_HALFS;
                load_chunk_W(nslot, nc * KCH, Whi, Wlo, tid);
                load_chunk_A(nslot, nc * KCH, Ahi, Alo, tid);
            }
            asm volatile("cp.async.commit_group;" ::: "memory");   // drain-safe

            const h16* slot = sbase + (size_t)(c % DEPTH) * SLOT_HALFS;
#pragma unroll
            for (int ks = 0; ks < 4; ++ks) {
                uint32_t ah[4], al[4];
                ldsm4(ah, slot + rowA * SR + ks * 16 + ahalf);
                ldsm4(al, slot + (64 + rowA) * SR + ks * 16 + ahalf);
#pragma unroll
                for (int np = 0; np < 2; ++np) {
                    uint32_t bh[4], bl[4];
                    int wr = 128 + wn * 32 + np * 16 + rowB;
                    ldsm4(bh, slot + wr * SR + ks * 16 + bhalf);
                    ldsm4(bl, slot + (wr + 128) * SR + ks * 16 + bhalf);
                    int f = np * 2;
                    // main: hi*hi in f32 acc
                    mma_f32acc(acc[f],     ah, bh[0], bh[1]);
                    mma_f32acc(acc[f + 1], ah, bh[2], bh[3]);
                    // cross: lo*hi + hi*lo, shared f16 acc (scaled x2048)
                    mma_f16acc(cacc[f],     al, bh[0], bh[1]);
                    mma_f16acc(cacc[f + 1], al, bh[2], bh[3]);
                    mma_f16acc(cacc[f],     ah, bl[0], bl[1]);
                    mma_f16acc(cacc[f + 1], ah, bl[2], bl[3]);
                }
            }
        }
        asm volatile("cp.async.wait_group 0;" ::: "memory");

        // ---- fold cross terms into main acc ----
#pragma unroll
        for (int f = 0; f < 4; ++f) {
            float2 c0 = __half22float2(*(const __half2*)&cacc[f][0]);
            float2 c1 = __half22float2(*(const __half2*)&cacc[f][1]);
            acc[f][0] += c0.x * INV_LOSCALE;
            acc[f][1] += c0.y * INV_LOSCALE;
            acc[f][2] += c1.x * INV_LOSCALE;
            acc[f][3] += c1.y * INV_LOSCALE;
        }

        // ---- store gate tile to global (parity-double-buffered) ----
        float* plane = g_gates + ((size_t)par * LAYERS * 6 + l * 6 + sl) * BH;
        {
            int gr = lane >> 2, t4 = lane & 3;
#pragma unroll
            for (int f = 0; f < 4; ++f) {
                int u = u0 + wn * 32 + f * 8 + t4 * 2;
                int r0 = wm * 16 + gr;
                *(float2*)(plane + (size_t)r0 * 1024 + u)       = make_float2(acc[f][0], acc[f][1]);
                *(float2*)(plane + (size_t)(r0 + 8) * 1024 + u) = make_float2(acc[f][2], acc[f][3]);
            }
        }

        // ---- group rendezvous: 6 CTAs of (l, ub) ----
        __syncthreads();
        if (tid == 0) {
            __threadfence();
            atomicAdd(&g_flag[l * 8 + ub], 1);
            spin_ge(&g_flag[l * 8 + ub], 6 * (t + 1));
        }
        __syncthreads();

        // ---- distributed pointwise GRU (slice sl of this ub's 8192 elems) ----
        const float* hsrc = g_h + ((size_t)l * 2 + par) * BH;
        float*       hdst = g_h + ((size_t)l * 2 + (par ^ 1)) * BH;
        h16* hhid = g_hhi + ((size_t)l * 2 + (par ^ 1)) * BH;
        h16* hlod = g_hlo + ((size_t)l * 2 + (par ^ 1)) * BH;
        const float* GI = g_gates + ((size_t)par * LAYERS * 6 + l * 6) * BH;
        const float* GH = GI + 3 * (size_t)BH;

        for (int e = start + tid; e < end; e += 512) {
            int b  = e >> 7;
            int u  = u0 + (e & 127);
            size_t ix = (size_t)b * 1024 + u;
            float gi_r = __ldcg(GI + ix),                  gh_r = __ldcg(GH + ix);
            float gi_z = __ldcg(GI + BH + ix),             gh_z = __ldcg(GH + BH + ix);
            float gi_n = __ldcg(GI + 2 * (size_t)BH + ix), gh_n = __ldcg(GH + 2 * (size_t)BH + ix);
            float pr = gi_r + bihp[u]           + gh_r + bhhp[u];
            float pz = gi_z + bihp[HID + u]     + gh_z + bhhp[HID + u];
            float rg = 1.f / (1.f + __expf(-pr));
            float zg = 1.f / (1.f + __expf(-pz));
            float nn = tanhf(gi_n + bihp[2 * HID + u] + rg * (gh_n + bhhp[2 * HID + u]));
            float hold = hsrc[ix];
            float hn = (1.f - zg) * nn + zg * hold;
            hdst[ix] = hn;
            h16 hi, lo;
            split2(hn, hi, lo);
            hhid[ix] = hi;
            hlod[ix] = lo;
            if (l == LAYERS - 1)
                out[(size_t)t * BH + ix] = hn;
        }

        // ---- release: this CTA completed step t ----
        __syncthreads();
        if (tid == 0) {
            __threadfence();
            atomicAdd(&g_lflag[l], 1);
        }
    }
}

// ---------------- launch -----------------------------------------------------
extern "C" void kernel_launch(void* const* d_in, const int* in_sizes, int n_in,
                              void* d_out, int out_size)
{
    const float* x   = (const float*)d_in[0];
    const float* h0  = (const float*)d_in[1];
    const float* wih = (const float*)d_in[2];
    const float* whh = (const float*)d_in[3];
    const float* bih = (const float*)d_in[4];
    const float* bhh = (const float*)d_in[5];
    float* out = (float*)d_out;

    cudaFuncSetAttribute(gru_persistent_kernel,
                         cudaFuncAttributeMaxDynamicSharedMemorySize, SMEM_REQ);

    {
        size_t n = (size_t)LAYERS * 3 * HID * HID;
        permute_weights_kernel<<<(unsigned)((n + 255) / 256), 256>>>(wih, whh);
    }
    {
        size_t n = (size_t)S_LEN * BH;
        split_x_kernel<<<(unsigned)((n + 255) / 256), 256>>>(x);
    }
    {
        size_t n = (size_t)LAYERS * BH;
        init_h_kernel<<<(unsigned)((n + 255) / 256), 256>>>(h0);  // + flag reset
    }
    gru_persistent_kernel<<<dim3(48, 3), 512, SMEM_REQ>>>(bih, bhh, out);
}

// round 12
// speedup vs baseline: 1.8703x; 1.1831x over previous
#include <cuda_runtime.h>
#include <cuda_fp16.h>
#include <cstdint>

#define S_LEN  512
#define BATCH  64
#define HID    1024
#define LAYERS 3
#define BH     (BATCH*HID)     // 65536
#define KCH    64              // K per chunk
#define CHUNKS 16              // 1024/64
#define DEPTH  3               // cp.async ring depth

#define SR     72              // smem row stride in halfs (144B)
// slot rows: [0,64) A, [64,192) W_hi, [192,320) W_lo
#define SLOT_HALFS (320*SR)            // 23040
#define SLOT_BYTES (SLOT_HALFS*2)      // 46080
#define SMEM_REQ (1024 + DEPTH*SLOT_BYTES)   // 139264 B

#define WBLK   (128*1024)      // one weight block: 128 rows x K=1024
#define LO_SCALE    2048.f
#define INV_LOSCALE (1.f/2048.f)

typedef __half h16;

// ---------------- device scratch (no runtime allocation) -------------------
__device__ h16 g_x  [(size_t)S_LEN*BH];          // f16 single-precision x
__device__ h16 g_wBhi[(size_t)LAYERS*2*3*8*WBLK];
__device__ h16 g_wBlo[(size_t)LAYERS*2*3*8*WBLK]; // (w - w_hi) * 2048
__device__ float g_h [LAYERS*2*BH];              // h state fp32, parity buffer
__device__ h16   g_hh[LAYERS*2*BH];              // h state f16 single
__device__ float g_gates[(size_t)2*LAYERS*6*BH]; // parity-double-buffered
__device__ int   g_flag[LAYERS*8];               // group rendezvous (l,ub)
__device__ int   g_lflag[LAYERS];                // per-layer completed-CTA count

// ---------------- helpers ----------------------------------------------------
__device__ __forceinline__ void ldsm4(uint32_t r[4], const h16* p) {
    uint32_t a = (uint32_t)__cvta_generic_to_shared(p);
    asm volatile("ldmatrix.sync.aligned.m8n8.x4.shared.b16 {%0,%1,%2,%3}, [%4];"
                 : "=r"(r[0]), "=r"(r[1]), "=r"(r[2]), "=r"(r[3]) : "r"(a));
}

// main product: f16 inputs, f32 accumulate
__device__ __forceinline__ void mma_f32acc(float c[4], const uint32_t a[4],
                                           uint32_t b0, uint32_t b1) {
    asm volatile("mma.sync.aligned.m16n8k16.row.col.f32.f16.f16.f32 "
                 "{%0,%1,%2,%3}, {%4,%5,%6,%7}, {%8,%9}, {%0,%1,%2,%3};"
                 : "+f"(c[0]), "+f"(c[1]), "+f"(c[2]), "+f"(c[3])
                 : "r"(a[0]), "r"(a[1]), "r"(a[2]), "r"(a[3]), "r"(b0), "r"(b1));
}

// correction product: f16 inputs, f16 accumulate (2 regs = 4 packed halfs)
__device__ __forceinline__ void mma_f16acc(uint32_t c[2], const uint32_t a[4],
                                           uint32_t b0, uint32_t b1) {
    asm volatile("mma.sync.aligned.m16n8k16.row.col.f16.f16.f16.f16 "
                 "{%0,%1}, {%2,%3,%4,%5}, {%6,%7}, {%0,%1};"
                 : "+r"(c[0]), "+r"(c[1])
                 : "r"(a[0]), "r"(a[1]), "r"(a[2]), "r"(a[3]), "r"(b0), "r"(b1));
}

// weight digit split: hi = f16(v); lo = f16((v - hi) * 2048)
__device__ __forceinline__ void wsplit(float v, h16& hi, h16& lo) {
    hi = __float2half_rn(v);
    lo = __float2half_rn((v - __half2float(hi)) * LO_SCALE);
}

__device__ __forceinline__ void cp16(h16* dst, const h16* src) {
    uint32_t d = (uint32_t)__cvta_generic_to_shared(dst);
    asm volatile("cp.async.cg.shared.global [%0], [%1], 16;" :: "r"(d), "l"(src));
}

__device__ __forceinline__ int ldacq(const int* p) {
    int v;
    asm volatile("ld.acquire.gpu.s32 %0, [%1];" : "=r"(v) : "l"(p) : "memory");
    return v;
}

__device__ __forceinline__ void spin_ge(const int* p, int target) {
    while (ldacq(p) < target) __nanosleep(64);
}

// ---------------- prep kernels ----------------------------------------------
__global__ void permute_weights_kernel(const float* __restrict__ wih,
                                       const float* __restrict__ whh) {
    size_t i = (size_t)blockIdx.x * blockDim.x + threadIdx.x;
    if (i >= (size_t)LAYERS * 3 * HID * HID) return;
    int k = (int)(i % HID);
    size_t row = i / HID;
    int l = (int)(row / (3 * HID));
    int r = (int)(row % (3 * HID));
    int g = r >> 10, u = r & 1023;
    int ub = u >> 7, rr = u & 127;
    size_t dih = ((size_t)(((l * 2 + 0) * 3 + g) * 8 + ub)) * WBLK + (size_t)rr * 1024 + k;
    size_t dhh = ((size_t)(((l * 2 + 1) * 3 + g) * 8 + ub)) * WBLK + (size_t)rr * 1024 + k;
    h16 hi, lo;
    wsplit(wih[i], hi, lo); g_wBhi[dih] = hi; g_wBlo[dih] = lo;
    wsplit(whh[i], hi, lo); g_wBhi[dhh] = hi; g_wBlo[dhh] = lo;
}

__global__ void cvt_x_kernel(const float* __restrict__ x) {
    size_t i = (size_t)blockIdx.x * blockDim.x + threadIdx.x;
    if (i >= (size_t)S_LEN * BH) return;
    g_x[i] = __float2half_rn(x[i]);
}

__global__ void init_h_kernel(const float* __restrict__ h0) {
    if (blockIdx.x == 0 && threadIdx.x < LAYERS * 8) {
        g_flag[threadIdx.x] = 0;
        if (threadIdx.x < LAYERS) g_lflag[threadIdx.x] = 0;
    }
    size_t i = (size_t)blockIdx.x * blockDim.x + threadIdx.x;
    if (i >= (size_t)LAYERS * BH) return;
    int l = (int)(i / BH);
    size_t j = i % BH;
    float v = h0[i];
    size_t dst = ((size_t)l * 2 + 0) * BH + j;
    g_h[dst]  = v;
    g_hh[dst] = __float2half_rn(v);
}

// ---------------- chunk loaders ---------------------------------------------
__device__ __forceinline__ void load_chunk_A(
    h16* slot, int kb, const h16* __restrict__ A, int tid)
{
    if (tid < 512) {
        int row = tid >> 3, c16 = tid & 7;   // 64 rows x 8 x 16B
        cp16(slot + row * SR + c16 * 8, A + (size_t)row * 1024 + kb + c16 * 8);
    }
}

__device__ __forceinline__ void load_chunk_W(
    h16* slot, int kb,
    const h16* __restrict__ Whi, const h16* __restrict__ Wlo, int tid)
{
#pragma unroll
    for (int i = tid; i < 2048; i += 512) {   // 2 planes x 128 rows x 8 x 16B
        int row = i >> 3, c16 = i & 7;
        int pl = row >> 7, r = row & 127;
        const h16* src = (pl ? Wlo : Whi) + (size_t)r * 1024 + kb + c16 * 8;
        cp16(slot + (64 + row) * SR + c16 * 8, src);
    }
}

// ---------------- persistent GRU kernel --------------------------------------
// grid (48, 3): l = blockIdx.y; q: p=q/24, g=(q%24)/8, ub=q%8. Each CTA loops
// t = 0..511 in its fixed role, synchronized by acquire/release flags.
// 2-product split: A single f16, W = hi + lo/2048 (f32acc + f16acc products).
__global__ __launch_bounds__(512) void gru_persistent_kernel(
    const float* __restrict__ bih, const float* __restrict__ bhh,
    float* __restrict__ out)
{
    const int l  = blockIdx.y;
    const int q  = blockIdx.x;
    const int p  = q / 24;
    const int g  = (q % 24) / 8;
    const int ub = q & 7;
    const int u0 = ub * 128;

    const int tid  = threadIdx.x;
    const int lane = tid & 31;
    const int wid  = tid >> 5;
    const int wm   = wid >> 2;
    const int wn   = wid & 3;

    extern __shared__ __align__(16) unsigned char smem_raw[];
    uint32_t dyn_u = (uint32_t)__cvta_generic_to_shared(smem_raw);
    uint32_t s0u   = (dyn_u + 1023u) & ~1023u;
    h16* sbase = (h16*)(smem_raw + (s0u - dyn_u));

    size_t wb = (size_t)(((l * 2 + p) * 3 + g) * 8 + ub) * WBLK;
    const h16* Whi = g_wBhi + wb;
    const h16* Wlo = g_wBlo + wb;

    const int rowA  = wm * 16 + (lane & 15);
    const int ahalf = (lane >> 4) * 8;
    const int rowB  = (lane & 7) + ((lane & 16) ? 8 : 0);
    const int bhalf = (lane & 8) ? 8 : 0;

    const int lG = l * 3 * HID;
    const float* bihp = bih + lG;
    const float* bhhp = bhh + lG;
    const int sl    = p * 3 + g;
    const int start = sl * 1366;
    const int end   = (start + 1366 < 8192) ? start + 1366 : 8192;

    for (int t = 0; t < S_LEN; ++t) {
        const int par = t & 1;

        const h16* A;
        if (p == 0) {
            if (l == 0) A = g_x + (size_t)t * BH;
            else        A = g_hh + ((size_t)(l - 1) * 2 + (par ^ 1)) * BH; // h_{l-1}[t]
        } else {
            A = g_hh + ((size_t)l * 2 + par) * BH;                         // h_l[t-1]
        }

        float acc[4][4];          // main product, f32
        uint32_t cacc[4][2];      // correction, packed f16 (scaled by 2048)
#pragma unroll
        for (int j = 0; j < 4; ++j) {
#pragma unroll
            for (int c = 0; c < 4; ++c) acc[j][c] = 0.f;
            cacc[j][0] = 0u; cacc[j][1] = 0u;
        }

        // ---- W of chunk 0 (no cross-step dependency) hides the flag spin ----
        load_chunk_W(sbase, 0, Whi, Wlo, tid);
        if (tid == 0) {
            spin_ge(&g_lflag[l], 48 * t);                       // own layer t-1 done
            if (p == 0 && l > 0) spin_ge(&g_lflag[l - 1], 48 * (t + 1));
            if (l < LAYERS - 1 && t >= 1) spin_ge(&g_lflag[l + 1], 48 * (t - 1));
        }
        __syncthreads();
        load_chunk_A(sbase, 0, A, tid);
        asm volatile("cp.async.commit_group;" ::: "memory");
        load_chunk_W(sbase + SLOT_HALFS, KCH, Whi, Wlo, tid);
        load_chunk_A(sbase + SLOT_HALFS, KCH, A, tid);
        asm volatile("cp.async.commit_group;" ::: "memory");

        // ---- main loop: 16 chunks, depth-3 ring ----
        for (int c = 0; c < CHUNKS; ++c) {
            asm volatile("cp.async.wait_group 1;" ::: "memory");
            __syncthreads();
            const int nc = c + DEPTH - 1;
            if (nc < CHUNKS) {
                h16* nslot = sbase + (size_t)(nc % DEPTH) * SLOT_HALFS;
                load_chunk_W(nslot, nc * KCH, Whi, Wlo, tid);
                load_chunk_A(nslot, nc * KCH, A, tid);
            }
            asm volatile("cp.async.commit_group;" ::: "memory");   // drain-safe

            const h16* slot = sbase + (size_t)(c % DEPTH) * SLOT_HALFS;
#pragma unroll
            for (int ks = 0; ks < 4; ++ks) {
                uint32_t a[4];
                ldsm4(a, slot + rowA * SR + ks * 16 + ahalf);
#pragma unroll
                for (int np = 0; np < 2; ++np) {
                    uint32_t wh[4], wl[4];
                    int wr = 64 + wn * 32 + np * 16 + rowB;
                    ldsm4(wh, slot + wr * SR + ks * 16 + bhalf);
                    ldsm4(wl, slot + (wr + 128) * SR + ks * 16 + bhalf);
                    int f = np * 2;
                    // main: a * w_hi in f32 acc
                    mma_f32acc(acc[f],     a, wh[0], wh[1]);
                    mma_f32acc(acc[f + 1], a, wh[2], wh[3]);
                    // correction: a * w_lo (x2048), f16 acc
                    mma_f16acc(cacc[f],     a, wl[0], wl[1]);
                    mma_f16acc(cacc[f + 1], a, wl[2], wl[3]);
                }
            }
        }
        asm volatile("cp.async.wait_group 0;" ::: "memory");

        // ---- fold correction into main acc ----
#pragma unroll
        for (int f = 0; f < 4; ++f) {
            float2 c0 = __half22float2(*(const __half2*)&cacc[f][0]);
            float2 c1 = __half22float2(*(const __half2*)&cacc[f][1]);
            acc[f][0] += c0.x * INV_LOSCALE;
            acc[f][1] += c0.y * INV_LOSCALE;
            acc[f][2] += c1.x * INV_LOSCALE;
            acc[f][3] += c1.y * INV_LOSCALE;
        }

        // ---- store gate tile to global (parity-double-buffered) ----
        float* plane = g_gates + ((size_t)par * LAYERS * 6 + l * 6 + sl) * BH;
        {
            int gr = lane >> 2, t4 = lane & 3;
#pragma unroll
            for (int f = 0; f < 4; ++f) {
                int u = u0 + wn * 32 + f * 8 + t4 * 2;
                int r0 = wm * 16 + gr;
                *(float2*)(plane + (size_t)r0 * 1024 + u)       = make_float2(acc[f][0], acc[f][1]);
                *(float2*)(plane + (size_t)(r0 + 8) * 1024 + u) = make_float2(acc[f][2], acc[f][3]);
            }
        }

        // ---- group rendezvous: 6 CTAs of (l, ub) ----
        __syncthreads();
        if (tid == 0) {
            __threadfence();
            atomicAdd(&g_flag[l * 8 + ub], 1);
            spin_ge(&g_flag[l * 8 + ub], 6 * (t + 1));
        }
        __syncthreads();

        // ---- distributed pointwise GRU (slice sl of this ub's 8192 elems) ----
        const float* hsrc = g_h + ((size_t)l * 2 + par) * BH;
        float*       hdst = g_h + ((size_t)l * 2 + (par ^ 1)) * BH;
        h16* hhd = g_hh + ((size_t)l * 2 + (par ^ 1)) * BH;
        const float* GI = g_gates + ((size_t)par * LAYERS * 6 + l * 6) * BH;
        const float* GH = GI + 3 * (size_t)BH;

        for (int e = start + tid; e < end; e += 512) {
            int b  = e >> 7;
            int u  = u0 + (e & 127);
            size_t ix = (size_t)b * 1024 + u;
            float gi_r = __ldcg(GI + ix),                  gh_r = __ldcg(GH + ix);
            float gi_z = __ldcg(GI + BH + ix),             gh_z = __ldcg(GH + BH + ix);
            float gi_n = __ldcg(GI + 2 * (size_t)BH + ix), gh_n = __ldcg(GH + 2 * (size_t)BH + ix);
            float pr = gi_r + bihp[u]           + gh_r + bhhp[u];
            float pz = gi_z + bihp[HID + u]     + gh_z + bhhp[HID + u];
            float rg = 1.f / (1.f + __expf(-pr));
            float zg = 1.f / (1.f + __expf(-pz));
            float nn = tanhf(gi_n + bihp[2 * HID + u] + rg * (gh_n + bhhp[2 * HID + u]));
            float hold = hsrc[ix];
            float hn = (1.f - zg) * nn + zg * hold;
            hdst[ix] = hn;
            hhd[ix]  = __float2half_rn(hn);
            if (l == LAYERS - 1)
                out[(size_t)t * BH + ix] = hn;
        }

        // ---- release: this CTA completed step t ----
        __syncthreads();
        if (tid == 0) {
            __threadfence();
            atomicAdd(&g_lflag[l], 1);
        }
    }
}

// ---------------- launch -----------------------------------------------------
extern "C" void kernel_launch(void* const* d_in, const int* in_sizes, int n_in,
                              void* d_out, int out_size)
{
    const float* x   = (const float*)d_in[0];
    const float* h0  = (const float*)d_in[1];
    const float* wih = (const float*)d_in[2];
    const float* whh = (const float*)d_in[3];
    const float* bih = (const float*)d_in[4];
    const float* bhh = (const float*)d_in[5];
    float* out = (float*)d_out;

    cudaFuncSetAttribute(gru_persistent_kernel,
                         cudaFuncAttributeMaxDynamicSharedMemorySize, SMEM_REQ);

    {
        size_t n = (size_t)LAYERS * 3 * HID * HID;
        permute_weights_kernel<<<(unsigned)((n + 255) / 256), 256>>>(wih, whh);
    }
    {
        size_t n = (size_t)S_LEN * BH;
        cvt_x_kernel<<<(unsigned)((n + 255) / 256), 256>>>(x);
    }
    {
        size_t n = (size_t)LAYERS * BH;
        init_h_kernel<<<(unsigned)((n + 255) / 256), 256>>>(h0);  // + flag reset
    }
    gru_persistent_kernel<<<dim3(48, 3), 512, SMEM_REQ>>>(bih, bhh, out);
}

// round 13
// speedup vs baseline: 1.9766x; 1.0568x over previous
#include <cuda_runtime.h>
#include <cuda_fp16.h>
#include <cstdint>

#define S_LEN  512
#define BATCH  64
#define HID    1024
#define LAYERS 3
#define BH     (BATCH*HID)     // 65536
#define KCH    64              // K per chunk
#define CHUNKS 16              // 1024/64
#define DEPTH  3               // cp.async ring depth

#define SR     72              // smem row stride in halfs (144B)
// slot rows: [0,64) A, [64,192) W_hi, [192,320) W_lo
#define SLOT_HALFS (320*SR)            // 23040
#define SLOT_BYTES (SLOT_HALFS*2)      // 46080
#define SMEM_REQ (1024 + DEPTH*SLOT_BYTES)   // 139264 B

#define WBLK   (128*1024)      // one weight block: 128 rows x K=1024
#define LO_SCALE    2048.f
#define INV_LOSCALE (1.f/2048.f)

typedef __half h16;

// ---------------- device scratch (no runtime allocation) -------------------
__device__ h16 g_x  [(size_t)S_LEN*BH];          // f16 single-precision x
__device__ h16 g_wBhi[(size_t)LAYERS*2*3*8*WBLK];
__device__ h16 g_wBlo[(size_t)LAYERS*2*3*8*WBLK]; // (w - w_hi) * 2048
__device__ float g_h [LAYERS*2*BH];              // h state fp32, parity buffer
__device__ h16   g_hh[LAYERS*2*BH];              // h state f16 single
__device__ float g_gates[(size_t)2*LAYERS*6*BH]; // parity-double-buffered
__device__ int   g_flag[LAYERS*8];               // group rendezvous (l,ub)
__device__ int   g_lflag[LAYERS];                // per-layer completed-CTA count

// ---------------- helpers ----------------------------------------------------
__device__ __forceinline__ void ldsm4(uint32_t r[4], const h16* p) {
    uint32_t a = (uint32_t)__cvta_generic_to_shared(p);
    asm volatile("ldmatrix.sync.aligned.m8n8.x4.shared.b16 {%0,%1,%2,%3}, [%4];"
                 : "=r"(r[0]), "=r"(r[1]), "=r"(r[2]), "=r"(r[3]) : "r"(a));
}

// main product: f16 inputs, f32 accumulate
__device__ __forceinline__ void mma_f32acc(float c[4], const uint32_t a[4],
                                           uint32_t b0, uint32_t b1) {
    asm volatile("mma.sync.aligned.m16n8k16.row.col.f32.f16.f16.f32 "
                 "{%0,%1,%2,%3}, {%4,%5,%6,%7}, {%8,%9}, {%0,%1,%2,%3};"
                 : "+f"(c[0]), "+f"(c[1]), "+f"(c[2]), "+f"(c[3])
                 : "r"(a[0]), "r"(a[1]), "r"(a[2]), "r"(a[3]), "r"(b0), "r"(b1));
}

// correction product: f16 inputs, f16 accumulate (2 regs = 4 packed halfs)
__device__ __forceinline__ void mma_f16acc(uint32_t c[2], const uint32_t a[4],
                                           uint32_t b0, uint32_t b1) {
    asm volatile("mma.sync.aligned.m16n8k16.row.col.f16.f16.f16.f16 "
                 "{%0,%1}, {%2,%3,%4,%5}, {%6,%7}, {%0,%1};"
                 : "+r"(c[0]), "+r"(c[1])
                 : "r"(a[0]), "r"(a[1]), "r"(a[2]), "r"(a[3]), "r"(b0), "r"(b1));
}

// weight digit split: hi = f16(v); lo = f16((v - hi) * 2048)
__device__ __forceinline__ void wsplit(float v, h16& hi, h16& lo) {
    hi = __float2half_rn(v);
    lo = __float2half_rn((v - __half2float(hi)) * LO_SCALE);
}

__device__ __forceinline__ void cp16(h16* dst, const h16* src) {
    uint32_t d = (uint32_t)__cvta_generic_to_shared(dst);
    asm volatile("cp.async.cg.shared.global [%0], [%1], 16;" :: "r"(d), "l"(src));
}

__device__ __forceinline__ int ldacq(const int* p) {
    int v;
    asm volatile("ld.acquire.gpu.s32 %0, [%1];" : "=r"(v) : "l"(p) : "memory");
    return v;
}

__device__ __forceinline__ void spin_ge(const int* p, int target) {
    while (ldacq(p) < target) __nanosleep(64);
}

// ---------------- prep kernels ----------------------------------------------
__global__ void permute_weights_kernel(const float* __restrict__ wih,
                                       const float* __restrict__ whh) {
    size_t i = (size_t)blockIdx.x * blockDim.x + threadIdx.x;
    if (i >= (size_t)LAYERS * 3 * HID * HID) return;
    int k = (int)(i % HID);
    size_t row = i / HID;
    int l = (int)(row / (3 * HID));
    int r = (int)(row % (3 * HID));
    int g = r >> 10, u = r & 1023;
    int ub = u >> 7, rr = u & 127;
    size_t dih = ((size_t)(((l * 2 + 0) * 3 + g) * 8 + ub)) * WBLK + (size_t)rr * 1024 + k;
    size_t dhh = ((size_t)(((l * 2 + 1) * 3 + g) * 8 + ub)) * WBLK + (size_t)rr * 1024 + k;
    h16 hi, lo;
    wsplit(wih[i], hi, lo); g_wBhi[dih] = hi; g_wBlo[dih] = lo;
    wsplit(whh[i], hi, lo); g_wBhi[dhh] = hi; g_wBlo[dhh] = lo;
}

__global__ void cvt_x_kernel(const float* __restrict__ x) {
    size_t i = (size_t)blockIdx.x * blockDim.x + threadIdx.x;
    if (i >= (size_t)S_LEN * BH) return;
    g_x[i] = __float2half_rn(x[i]);
}

__global__ void init_h_kernel(const float* __restrict__ h0) {
    if (blockIdx.x == 0 && threadIdx.x < LAYERS * 8) {
        g_flag[threadIdx.x] = 0;
        if (threadIdx.x < LAYERS) g_lflag[threadIdx.x] = 0;
    }
    size_t i = (size_t)blockIdx.x * blockDim.x + threadIdx.x;
    if (i >= (size_t)LAYERS * BH) return;
    int l = (int)(i / BH);
    size_t j = i % BH;
    float v = h0[i];
    size_t dst = ((size_t)l * 2 + 0) * BH + j;
    g_h[dst]  = v;
    g_hh[dst] = __float2half_rn(v);
}

// ---------------- chunk loaders ---------------------------------------------
__device__ __forceinline__ void load_chunk_A(
    h16* slot, int kb, const h16* __restrict__ A, int tid)
{
    if (tid < 512) {
        int row = tid >> 3, c16 = tid & 7;   // 64 rows x 8 x 16B
        cp16(slot + row * SR + c16 * 8, A + (size_t)row * 1024 + kb + c16 * 8);
    }
}

// with_lo: load the W_lo plane only for chunks that run the correction MMA
__device__ __forceinline__ void load_chunk_W(
    h16* slot, int kb,
    const h16* __restrict__ Whi, const h16* __restrict__ Wlo, int tid,
    bool with_lo)
{
#pragma unroll
    for (int i = tid; i < 1024; i += 512) {   // W_hi: 128 rows x 8 x 16B
        int row = i >> 3, c16 = i & 7;
        cp16(slot + (64 + row) * SR + c16 * 8,
             Whi + (size_t)row * 1024 + kb + c16 * 8);
    }
    if (with_lo) {
#pragma unroll
        for (int i = tid; i < 1024; i += 512) {   // W_lo plane
            int row = i >> 3, c16 = i & 7;
            cp16(slot + (192 + row) * SR + c16 * 8,
                 Wlo + (size_t)row * 1024 + kb + c16 * 8);
        }
    }
}

// ---------------- persistent GRU kernel --------------------------------------
// grid (48, 3): l = blockIdx.y; q: p=q/24, g=(q%24)/8, ub=q%8. Each CTA loops
// t = 0..511 in its fixed role, synchronized by acquire/release flags.
// 2-product split; w_lo correction applied on even chunks only (K=512 of 1024).
__global__ __launch_bounds__(512) void gru_persistent_kernel(
    const float* __restrict__ bih, const float* __restrict__ bhh,
    float* __restrict__ out)
{
    const int l  = blockIdx.y;
    const int q  = blockIdx.x;
    const int p  = q / 24;
    const int g  = (q % 24) / 8;
    const int ub = q & 7;
    const int u0 = ub * 128;

    const int tid  = threadIdx.x;
    const int lane = tid & 31;
    const int wid  = tid >> 5;
    const int wm   = wid >> 2;
    const int wn   = wid & 3;

    extern __shared__ __align__(16) unsigned char smem_raw[];
    uint32_t dyn_u = (uint32_t)__cvta_generic_to_shared(smem_raw);
    uint32_t s0u   = (dyn_u + 1023u) & ~1023u;
    h16* sbase = (h16*)(smem_raw + (s0u - dyn_u));

    size_t wb = (size_t)(((l * 2 + p) * 3 + g) * 8 + ub) * WBLK;
    const h16* Whi = g_wBhi + wb;
    const h16* Wlo = g_wBlo + wb;

    const int rowA  = wm * 16 + (lane & 15);
    const int ahalf = (lane >> 4) * 8;
    const int rowB  = (lane & 7) + ((lane & 16) ? 8 : 0);
    const int bhalf = (lane & 8) ? 8 : 0;

    const int lG = l * 3 * HID;
    const float* bihp = bih + lG;
    const float* bhhp = bhh + lG;
    const int sl    = p * 3 + g;
    const int start = sl * 1366;
    const int end   = (start + 1366 < 8192) ? start + 1366 : 8192;

    for (int t = 0; t < S_LEN; ++t) {
        const int par = t & 1;

        const h16* A;
        if (p == 0) {
            if (l == 0) A = g_x + (size_t)t * BH;
            else        A = g_hh + ((size_t)(l - 1) * 2 + (par ^ 1)) * BH; // h_{l-1}[t]
        } else {
            A = g_hh + ((size_t)l * 2 + par) * BH;                         // h_l[t-1]
        }

        float acc[4][4];          // main product, f32
        uint32_t cacc[4][2];      // correction, packed f16 (scaled by 2048)
#pragma unroll
        for (int j = 0; j < 4; ++j) {
#pragma unroll
            for (int c = 0; c < 4; ++c) acc[j][c] = 0.f;
            cacc[j][0] = 0u; cacc[j][1] = 0u;
        }

        // ---- W of chunk 0 (no cross-step dependency) hides the flag spin ----
        load_chunk_W(sbase, 0, Whi, Wlo, tid, true);          // chunk 0: corr
        if (tid == 0) {
            spin_ge(&g_lflag[l], 48 * t);                       // own layer t-1 done
            if (p == 0 && l > 0) spin_ge(&g_lflag[l - 1], 48 * (t + 1));
            if (l < LAYERS - 1 && t >= 1) spin_ge(&g_lflag[l + 1], 48 * (t - 1));
        }
        __syncthreads();
        load_chunk_A(sbase, 0, A, tid);
        asm volatile("cp.async.commit_group;" ::: "memory");
        load_chunk_W(sbase + SLOT_HALFS, KCH, Whi, Wlo, tid, false); // chunk 1: no corr
        load_chunk_A(sbase + SLOT_HALFS, KCH, A, tid);
        asm volatile("cp.async.commit_group;" ::: "memory");

        // ---- main loop: 16 chunks, depth-3 ring ----
        for (int c = 0; c < CHUNKS; ++c) {
            asm volatile("cp.async.wait_group 1;" ::: "memory");
            __syncthreads();
            const int nc = c + DEPTH - 1;
            if (nc < CHUNKS) {
                h16* nslot = sbase + (size_t)(nc % DEPTH) * SLOT_HALFS;
                load_chunk_W(nslot, nc * KCH, Whi, Wlo, tid, (nc & 1) == 0);
                load_chunk_A(nslot, nc * KCH, A, tid);
            }
            asm volatile("cp.async.commit_group;" ::: "memory");   // drain-safe

            const h16* slot = sbase + (size_t)(c % DEPTH) * SLOT_HALFS;
            const bool corr = (c & 1) == 0;
#pragma unroll
            for (int ks = 0; ks < 4; ++ks) {
                uint32_t a[4];
                ldsm4(a, slot + rowA * SR + ks * 16 + ahalf);
#pragma unroll
                for (int np = 0; np < 2; ++np) {
                    uint32_t wh[4];
                    int wr = 64 + wn * 32 + np * 16 + rowB;
                    ldsm4(wh, slot + wr * SR + ks * 16 + bhalf);
                    int f = np * 2;
                    // main: a * w_hi in f32 acc
                    mma_f32acc(acc[f],     a, wh[0], wh[1]);
                    mma_f32acc(acc[f + 1], a, wh[2], wh[3]);
                    if (corr) {
                        uint32_t wl[4];
                        ldsm4(wl, slot + (wr + 128) * SR + ks * 16 + bhalf);
                        // correction: a * w_lo (x2048), f16 acc
                        mma_f16acc(cacc[f],     a, wl[0], wl[1]);
                        mma_f16acc(cacc[f + 1], a, wl[2], wl[3]);
                    }
                }
            }
        }
        asm volatile("cp.async.wait_group 0;" ::: "memory");

        // ---- fold correction into main acc ----
#pragma unroll
        for (int f = 0; f < 4; ++f) {
            float2 c0 = __half22float2(*(const __half2*)&cacc[f][0]);
            float2 c1 = __half22float2(*(const __half2*)&cacc[f][1]);
            acc[f][0] += c0.x * INV_LOSCALE;
            acc[f][1] += c0.y * INV_LOSCALE;
            acc[f][2] += c1.x * INV_LOSCALE;
            acc[f][3] += c1.y * INV_LOSCALE;
        }

        // ---- store gate tile to global (parity-double-buffered) ----
        float* plane = g_gates + ((size_t)par * LAYERS * 6 + l * 6 + sl) * BH;
        {
            int gr = lane >> 2, t4 = lane & 3;
#pragma unroll
            for (int f = 0; f < 4; ++f) {
                int u = u0 + wn * 32 + f * 8 + t4 * 2;
                int r0 = wm * 16 + gr;
                *(float2*)(plane + (size_t)r0 * 1024 + u)       = make_float2(acc[f][0], acc[f][1]);
                *(float2*)(plane + (size_t)(r0 + 8) * 1024 + u) = make_float2(acc[f][2], acc[f][3]);
            }
        }

        // ---- group rendezvous: 6 CTAs of (l, ub) ----
        __syncthreads();
        if (tid == 0) {
            __threadfence();
            atomicAdd(&g_flag[l * 8 + ub], 1);
            spin_ge(&g_flag[l * 8 + ub], 6 * (t + 1));
        }
        __syncthreads();

        // ---- distributed pointwise GRU (slice sl of this ub's 8192 elems) ----
        const float* hsrc = g_h + ((size_t)l * 2 + par) * BH;
        float*       hdst = g_h + ((size_t)l * 2 + (par ^ 1)) * BH;
        h16* hhd = g_hh + ((size_t)l * 2 + (par ^ 1)) * BH;
        const float* GI = g_gates + ((size_t)par * LAYERS * 6 + l * 6) * BH;
        const float* GH = GI + 3 * (size_t)BH;

        for (int e = start + tid; e < end; e += 512) {
            int b  = e >> 7;
            int u  = u0 + (e & 127);
            size_t ix = (size_t)b * 1024 + u;
            float gi_r = __ldcg(GI + ix),                  gh_r = __ldcg(GH + ix);
            float gi_z = __ldcg(GI + BH + ix),             gh_z = __ldcg(GH + BH + ix);
            float gi_n = __ldcg(GI + 2 * (size_t)BH + ix), gh_n = __ldcg(GH + 2 * (size_t)BH + ix);
            float pr = gi_r + bihp[u]           + gh_r + bhhp[u];
            float pz = gi_z + bihp[HID + u]     + gh_z + bhhp[HID + u];
            float rg = 1.f / (1.f + __expf(-pr));
            float zg = 1.f / (1.f + __expf(-pz));
            float nn = tanhf(gi_n + bihp[2 * HID + u] + rg * (gh_n + bhhp[2 * HID + u]));
            float hold = hsrc[ix];
            float hn = (1.f - zg) * nn + zg * hold;
            hdst[ix] = hn;
            hhd[ix]  = __float2half_rn(hn);
            if (l == LAYERS - 1)
                out[(size_t)t * BH + ix] = hn;
        }

        // ---- release: this CTA completed step t ----
        __syncthreads();
        if (tid == 0) {
            __threadfence();
            atomicAdd(&g_lflag[l], 1);
        }
    }
}

// ---------------- launch -----------------------------------------------------
extern "C" void kernel_launch(void* const* d_in, const int* in_sizes, int n_in,
                              void* d_out, int out_size)
{
    const float* x   = (const float*)d_in[0];
    const float* h0  = (const float*)d_in[1];
    const float* wih = (const float*)d_in[2];
    const float* whh = (const float*)d_in[3];
    const float* bih = (const float*)d_in[4];
    const float* bhh = (const float*)d_in[5];
    float* out = (float*)d_out;

    cudaFuncSetAttribute(gru_persistent_kernel,
                         cudaFuncAttributeMaxDynamicSharedMemorySize, SMEM_REQ);

    {
        size_t n = (size_t)LAYERS * 3 * HID * HID;
        permute_weights_kernel<<<(unsigned)((n + 255) / 256), 256>>>(wih, whh);
    }
    {
        size_t n = (size_t)S_LEN * BH;
        cvt_x_kernel<<<(unsigned)((n + 255) / 256), 256>>>(x);
    }
    {
        size_t n = (size_t)LAYERS * BH;
        init_h_kernel<<<(unsigned)((n + 255) / 256), 256>>>(h0);  // + flag reset
    }
    gru_persistent_kernel<<<dim3(48, 3), 512, SMEM_REQ>>>(bih, bhh, out);
}

// round 14
// speedup vs baseline: 2.8715x; 1.4527x over previous
#include <cuda_runtime.h>
#include <cuda_fp16.h>
#include <cstdint>

#define S_LEN  512
#define BATCH  64
#define HID    1024
#define LAYERS 3
#define BH     (BATCH*HID)     // 65536
#define KCH    64              // K per chunk
#define CHUNKS 16              // 1024/64
#define DEPTH  3               // cp.async ring depth

#define SR     72              // smem row stride in halfs (144B)
// slot rows: [0,64) A, [64,192) W_hi
#define SLOT_HALFS (192*SR)            // 13824
#define SLOT_BYTES (SLOT_HALFS*2)      // 27648
#define SMEM_REQ (1024 + DEPTH*SLOT_BYTES)   // 83968 B

#define WBLK   (128*1024)      // one weight block: 128 rows x K=1024

typedef __half h16;

// ---------------- device scratch (no runtime allocation) -------------------
__device__ h16 g_x  [(size_t)S_LEN*BH];          // f16 x
__device__ h16 g_wB [(size_t)LAYERS*2*3*8*WBLK]; // f16 weights, tile-contiguous
__device__ float g_h [LAYERS*2*BH];              // h state fp32, parity buffer
__device__ h16   g_hh[LAYERS*2*BH];              // h state f16
__device__ float g_gates[(size_t)2*LAYERS*6*BH]; // parity-double-buffered
__device__ int   g_flag[LAYERS*8];               // group rendezvous (l,ub)
__device__ int   g_lflag[LAYERS];                // per-layer completed-CTA count

// ---------------- helpers ----------------------------------------------------
__device__ __forceinline__ void ldsm4(uint32_t r[4], const h16* p) {
    uint32_t a = (uint32_t)__cvta_generic_to_shared(p);
    asm volatile("ldmatrix.sync.aligned.m8n8.x4.shared.b16 {%0,%1,%2,%3}, [%4];"
                 : "=r"(r[0]), "=r"(r[1]), "=r"(r[2]), "=r"(r[3]) : "r"(a));
}

__device__ __forceinline__ void mma_f32acc(float c[4], const uint32_t a[4],
                                           uint32_t b0, uint32_t b1) {
    asm volatile("mma.sync.aligned.m16n8k16.row.col.f32.f16.f16.f32 "
                 "{%0,%1,%2,%3}, {%4,%5,%6,%7}, {%8,%9}, {%0,%1,%2,%3};"
                 : "+f"(c[0]), "+f"(c[1]), "+f"(c[2]), "+f"(c[3])
                 : "r"(a[0]), "r"(a[1]), "r"(a[2]), "r"(a[3]), "r"(b0), "r"(b1));
}

__device__ __forceinline__ void cp16(h16* dst, const h16* src) {
    uint32_t d = (uint32_t)__cvta_generic_to_shared(dst);
    asm volatile("cp.async.cg.shared.global [%0], [%1], 16;" :: "r"(d), "l"(src));
}

__device__ __forceinline__ int ldacq(const int* p) {
    int v;
    asm volatile("ld.acquire.gpu.s32 %0, [%1];" : "=r"(v) : "l"(p) : "memory");
    return v;
}

__device__ __forceinline__ void spin_ge(const int* p, int target) {
    while (ldacq(p) < target) __nanosleep(64);
}

// ---------------- prep kernels ----------------------------------------------
__global__ void permute_weights_kernel(const float* __restrict__ wih,
                                       const float* __restrict__ whh) {
    size_t i = (size_t)blockIdx.x * blockDim.x + threadIdx.x;
    if (i >= (size_t)LAYERS * 3 * HID * HID) return;
    int k = (int)(i % HID);
    size_t row = i / HID;
    int l = (int)(row / (3 * HID));
    int r = (int)(row % (3 * HID));
    int g = r >> 10, u = r & 1023;
    int ub = u >> 7, rr = u & 127;
    size_t dih = ((size_t)(((l * 2 + 0) * 3 + g) * 8 + ub)) * WBLK + (size_t)rr * 1024 + k;
    size_t dhh = ((size_t)(((l * 2 + 1) * 3 + g) * 8 + ub)) * WBLK + (size_t)rr * 1024 + k;
    g_wB[dih] = __float2half_rn(wih[i]);
    g_wB[dhh] = __float2half_rn(whh[i]);
}

__global__ void cvt_x_kernel(const float* __restrict__ x) {
    size_t i = (size_t)blockIdx.x * blockDim.x + threadIdx.x;
    if (i >= (size_t)S_LEN * BH) return;
    g_x[i] = __float2half_rn(x[i]);
}

__global__ void init_h_kernel(const float* __restrict__ h0) {
    if (blockIdx.x == 0 && threadIdx.x < LAYERS * 8) {
        g_flag[threadIdx.x] = 0;
        if (threadIdx.x < LAYERS) g_lflag[threadIdx.x] = 0;
    }
    size_t i = (size_t)blockIdx.x * blockDim.x + threadIdx.x;
    if (i >= (size_t)LAYERS * BH) return;
    int l = (int)(i / BH);
    size_t j = i % BH;
    float v = h0[i];
    size_t dst = ((size_t)l * 2 + 0) * BH + j;
    g_h[dst]  = v;
    g_hh[dst] = __float2half_rn(v);
}

// ---------------- chunk loaders ---------------------------------------------
__device__ __forceinline__ void load_chunk_A(
    h16* slot, int kb, const h16* __restrict__ A, int tid)
{
    if (tid < 512) {
        int row = tid >> 3, c16 = tid & 7;   // 64 rows x 8 x 16B
        cp16(slot + row * SR + c16 * 8, A + (size_t)row * 1024 + kb + c16 * 8);
    }
}

__device__ __forceinline__ void load_chunk_W(
    h16* slot, int kb, const h16* __restrict__ W, int tid)
{
#pragma unroll
    for (int i = tid; i < 1024; i += 512) {   // 128 rows x 8 x 16B
        int row = i >> 3, c16 = i & 7;
        cp16(slot + (64 + row) * SR + c16 * 8,
             W + (size_t)row * 1024 + kb + c16 * 8);
    }
}

// ---------------- persistent GRU kernel --------------------------------------
// grid (48, 3): l = blockIdx.y; q: p=q/24, g=(q%24)/8, ub=q%8. Each CTA loops
// t = 0..511 in its fixed role, synchronized by acquire/release flags.
// Single f16 product (f32 accumulate) — minimal-MMA configuration.
__global__ __launch_bounds__(512) void gru_persistent_kernel(
    const float* __restrict__ bih, const float* __restrict__ bhh,
    float* __restrict__ out)
{
    const int l  = blockIdx.y;
    const int q  = blockIdx.x;
    const int p  = q / 24;
    const int g  = (q % 24) / 8;
    const int ub = q & 7;
    const int u0 = ub * 128;

    const int tid  = threadIdx.x;
    const int lane = tid & 31;
    const int wid  = tid >> 5;
    const int wm   = wid >> 2;
    const int wn   = wid & 3;

    extern __shared__ __align__(16) unsigned char smem_raw[];
    uint32_t dyn_u = (uint32_t)__cvta_generic_to_shared(smem_raw);
    uint32_t s0u   = (dyn_u + 1023u) & ~1023u;
    h16* sbase = (h16*)(smem_raw + (s0u - dyn_u));

    size_t wb = (size_t)(((l * 2 + p) * 3 + g) * 8 + ub) * WBLK;
    const h16* W = g_wB + wb;

    const int rowA  = wm * 16 + (lane & 15);
    const int ahalf = (lane >> 4) * 8;
    const int rowB  = (lane & 7) + ((lane & 16) ? 8 : 0);
    const int bhalf = (lane & 8) ? 8 : 0;

    const int lG = l * 3 * HID;
    const float* bihp = bih + lG;
    const float* bhhp = bhh + lG;
    const int sl    = p * 3 + g;
    const int start = sl * 1366;
    const int end   = (start + 1366 < 8192) ? start + 1366 : 8192;

    for (int t = 0; t < S_LEN; ++t) {
        const int par = t & 1;

        const h16* A;
        if (p == 0) {
            if (l == 0) A = g_x + (size_t)t * BH;
            else        A = g_hh + ((size_t)(l - 1) * 2 + (par ^ 1)) * BH; // h_{l-1}[t]
        } else {
            A = g_hh + ((size_t)l * 2 + par) * BH;                         // h_l[t-1]
        }

        float acc[4][4];
#pragma unroll
        for (int j = 0; j < 4; ++j)
#pragma unroll
            for (int c = 0; c < 4; ++c) acc[j][c] = 0.f;

        // ---- W of chunk 0 (no cross-step dependency) hides the flag spin ----
        load_chunk_W(sbase, 0, W, tid);
        if (tid == 0) {
            spin_ge(&g_lflag[l], 48 * t);                       // own layer t-1 done
            if (p == 0 && l > 0) spin_ge(&g_lflag[l - 1], 48 * (t + 1));
            if (l < LAYERS - 1 && t >= 1) spin_ge(&g_lflag[l + 1], 48 * (t - 1));
        }
        __syncthreads();
        load_chunk_A(sbase, 0, A, tid);
        asm volatile("cp.async.commit_group;" ::: "memory");
        load_chunk_W(sbase + SLOT_HALFS, KCH, W, tid);
        load_chunk_A(sbase + SLOT_HALFS, KCH, A, tid);
        asm volatile("cp.async.commit_group;" ::: "memory");

        // ---- main loop: 16 chunks, depth-3 ring ----
        for (int c = 0; c < CHUNKS; ++c) {
            asm volatile("cp.async.wait_group 1;" ::: "memory");
            __syncthreads();
            const int nc = c + DEPTH - 1;
            if (nc < CHUNKS) {
                h16* nslot = sbase + (size_t)(nc % DEPTH) * SLOT_HALFS;
                load_chunk_W(nslot, nc * KCH, W, tid);
                load_chunk_A(nslot, nc * KCH, A, tid);
            }
            asm volatile("cp.async.commit_group;" ::: "memory");   // drain-safe

            const h16* slot = sbase + (size_t)(c % DEPTH) * SLOT_HALFS;
#pragma unroll
            for (int ks = 0; ks < 4; ++ks) {
                uint32_t a[4];
                ldsm4(a, slot + rowA * SR + ks * 16 + ahalf);
#pragma unroll
                for (int np = 0; np < 2; ++np) {
                    uint32_t wh[4];
                    int wr = 64 + wn * 32 + np * 16 + rowB;
                    ldsm4(wh, slot + wr * SR + ks * 16 + bhalf);
                    int f = np * 2;
                    mma_f32acc(acc[f],     a, wh[0], wh[1]);
                    mma_f32acc(acc[f + 1], a, wh[2], wh[3]);
                }
            }
        }
        asm volatile("cp.async.wait_group 0;" ::: "memory");

        // ---- store gate tile to global (parity-double-buffered) ----
        float* plane = g_gates + ((size_t)par * LAYERS * 6 + l * 6 + sl) * BH;
        {
            int gr = lane >> 2, t4 = lane & 3;
#pragma unroll
            for (int f = 0; f < 4; ++f) {
                int u = u0 + wn * 32 + f * 8 + t4 * 2;
                int r0 = wm * 16 + gr;
                *(float2*)(plane + (size_t)r0 * 1024 + u)       = make_float2(acc[f][0], acc[f][1]);
                *(float2*)(plane + (size_t)(r0 + 8) * 1024 + u) = make_float2(acc[f][2], acc[f][3]);
            }
        }

        // ---- group rendezvous: 6 CTAs of (l, ub) ----
        __syncthreads();
        if (tid == 0) {
            __threadfence();
            atomicAdd(&g_flag[l * 8 + ub], 1);
            spin_ge(&g_flag[l * 8 + ub], 6 * (t + 1));
        }
        __syncthreads();

        // ---- distributed pointwise GRU (slice sl of this ub's 8192 elems) ----
        const float* hsrc = g_h + ((size_t)l * 2 + par) * BH;
        float*       hdst = g_h + ((size_t)l * 2 + (par ^ 1)) * BH;
        h16* hhd = g_hh + ((size_t)l * 2 + (par ^ 1)) * BH;
        const float* GI = g_gates + ((size_t)par * LAYERS * 6 + l * 6) * BH;
        const float* GH = GI + 3 * (size_t)BH;

        for (int e = start + tid; e < end; e += 512) {
            int b  = e >> 7;
            int u  = u0 + (e & 127);
            size_t ix = (size_t)b * 1024 + u;
            float gi_r = __ldcg(GI + ix),                  gh_r = __ldcg(GH + ix);
            float gi_z = __ldcg(GI + BH + ix),             gh_z = __ldcg(GH + BH + ix);
            float gi_n = __ldcg(GI + 2 * (size_t)BH + ix), gh_n = __ldcg(GH + 2 * (size_t)BH + ix);
            float pr = gi_r + bihp[u]           + gh_r + bhhp[u];
            float pz = gi_z + bihp[HID + u]     + gh_z + bhhp[HID + u];
            float rg = 1.f / (1.f + __expf(-pr));
            float zg = 1.f / (1.f + __expf(-pz));
            float nn = tanhf(gi_n + bihp[2 * HID + u] + rg * (gh_n + bhhp[2 * HID + u]));
            float hold = hsrc[ix];
            float hn = (1.f - zg) * nn + zg * hold;
            hdst[ix] = hn;
            hhd[ix]  = __float2half_rn(hn);
            if (l == LAYERS - 1)
                out[(size_t)t * BH + ix] = hn;
        }

        // ---- release: this CTA completed step t ----
        __syncthreads();
        if (tid == 0) {
            __threadfence();
            atomicAdd(&g_lflag[l], 1);
        }
    }
}

// ---------------- launch -----------------------------------------------------
extern "C" void kernel_launch(void* const* d_in, const int* in_sizes, int n_in,
                              void* d_out, int out_size)
{
    const float* x   = (const float*)d_in[0];
    const float* h0  = (const float*)d_in[1];
    const float* wih = (const float*)d_in[2];
    const float* whh = (const float*)d_in[3];
    const float* bih = (const float*)d_in[4];
    const float* bhh = (const float*)d_in[5];
    float* out = (float*)d_out;

    cudaFuncSetAttribute(gru_persistent_kernel,
                         cudaFuncAttributeMaxDynamicSharedMemorySize, SMEM_REQ);

    {
        size_t n = (size_t)LAYERS * 3 * HID * HID;
        permute_weights_kernel<<<(unsigned)((n + 255) / 256), 256>>>(wih, whh);
    }
    {
        size_t n = (size_t)S_LEN * BH;
        cvt_x_kernel<<<(unsigned)((n + 255) / 256), 256>>>(x);
    }
    {
        size_t n = (size_t)LAYERS * BH;
        init_h_kernel<<<(unsigned)((n + 255) / 256), 256>>>(h0);  // + flag reset
    }
    gru_persistent_kernel<<<dim3(48, 3), 512, SMEM_REQ>>>(bih, bhh, out);
}

// round 15
// speedup vs baseline: 2.9232x; 1.0180x over previous
#include <cuda_runtime.h>
#include <cuda_fp16.h>
#include <cstdint>

#define S_LEN  512
#define BATCH  64
#define HID    1024
#define LAYERS 3
#define BH     (BATCH*HID)     // 65536
#define KCH    64              // K per chunk
#define CHUNKS 16              // 1024/64
#define DEPTH  3               // cp.async ring depth
#define NPIN   6               // W chunks pinned in smem (kb 0..5)

#define SR     72              // smem row stride in halfs (144B)
// ring slot rows: [0,64) A, [64,192) W (streamed chunks only)
#define SLOT_HALFS (192*SR)              // 13824
#define RING_HALFS (DEPTH*SLOT_HALFS)    // 41472
#define PINC_HALFS (128*SR)              // 9216 per pinned W chunk
#define PIN_HALFS  (NPIN*PINC_HALFS)     // 55296
#define SMEM_REQ (1024 + (RING_HALFS + PIN_HALFS)*2)   // 194560 B

#define WBLK   (128*1024)      // one weight block: 128 rows x K=1024

typedef __half h16;

// ---------------- device scratch (no runtime allocation) -------------------
__device__ h16 g_x  [(size_t)S_LEN*BH];          // f16 x
__device__ h16 g_wB [(size_t)LAYERS*2*3*8*WBLK]; // f16 weights, tile-contiguous
__device__ float g_h [LAYERS*2*BH];              // h state fp32, parity buffer
__device__ h16   g_hh[LAYERS*2*BH];              // h state f16
__device__ float g_gates[(size_t)2*LAYERS*6*BH]; // parity-double-buffered
__device__ int   g_flag[LAYERS*8];               // group rendezvous (l,ub)
__device__ int   g_lflag[LAYERS];                // per-layer completed-CTA count

// ---------------- helpers ----------------------------------------------------
__device__ __forceinline__ void ldsm4(uint32_t r[4], const h16* p) {
    uint32_t a = (uint32_t)__cvta_generic_to_shared(p);
    asm volatile("ldmatrix.sync.aligned.m8n8.x4.shared.b16 {%0,%1,%2,%3}, [%4];"
                 : "=r"(r[0]), "=r"(r[1]), "=r"(r[2]), "=r"(r[3]) : "r"(a));
}

__device__ __forceinline__ void mma_f32acc(float c[4], const uint32_t a[4],
                                           uint32_t b0, uint32_t b1) {
    asm volatile("mma.sync.aligned.m16n8k16.row.col.f32.f16.f16.f32 "
                 "{%0,%1,%2,%3}, {%4,%5,%6,%7}, {%8,%9}, {%0,%1,%2,%3};"
                 : "+f"(c[0]), "+f"(c[1]), "+f"(c[2]), "+f"(c[3])
                 : "r"(a[0]), "r"(a[1]), "r"(a[2]), "r"(a[3]), "r"(b0), "r"(b1));
}

__device__ __forceinline__ void cp16(h16* dst, const h16* src) {
    uint32_t d = (uint32_t)__cvta_generic_to_shared(dst);
    asm volatile("cp.async.cg.shared.global [%0], [%1], 16;" :: "r"(d), "l"(src));
}

__device__ __forceinline__ int ldacq(const int* p) {
    int v;
    asm volatile("ld.acquire.gpu.s32 %0, [%1];" : "=r"(v) : "l"(p) : "memory");
    return v;
}

__device__ __forceinline__ void spin_ge(const int* p, int target) {
    while (ldacq(p) < target) __nanosleep(64);
}

// ---------------- prep kernels ----------------------------------------------
__global__ void permute_weights_kernel(const float* __restrict__ wih,
                                       const float* __restrict__ whh) {
    size_t i = (size_t)blockIdx.x * blockDim.x + threadIdx.x;
    if (i >= (size_t)LAYERS * 3 * HID * HID) return;
    int k = (int)(i % HID);
    size_t row = i / HID;
    int l = (int)(row / (3 * HID));
    int r = (int)(row % (3 * HID));
    int g = r >> 10, u = r & 1023;
    int ub = u >> 7, rr = u & 127;
    size_t dih = ((size_t)(((l * 2 + 0) * 3 + g) * 8 + ub)) * WBLK + (size_t)rr * 1024 + k;
    size_t dhh = ((size_t)(((l * 2 + 1) * 3 + g) * 8 + ub)) * WBLK + (size_t)rr * 1024 + k;
    g_wB[dih] = __float2half_rn(wih[i]);
    g_wB[dhh] = __float2half_rn(whh[i]);
}

__global__ void cvt_x_kernel(const float* __restrict__ x) {
    size_t i = (size_t)blockIdx.x * blockDim.x + threadIdx.x;
    if (i >= (size_t)S_LEN * BH) return;
    g_x[i] = __float2half_rn(x[i]);
}

__global__ void init_h_kernel(const float* __restrict__ h0) {
    if (blockIdx.x == 0 && threadIdx.x < LAYERS * 8) {
        g_flag[threadIdx.x] = 0;
        if (threadIdx.x < LAYERS) g_lflag[threadIdx.x] = 0;
    }
    size_t i = (size_t)blockIdx.x * blockDim.x + threadIdx.x;
    if (i >= (size_t)LAYERS * BH) return;
    int l = (int)(i / BH);
    size_t j = i % BH;
    float v = h0[i];
    size_t dst = ((size_t)l * 2 + 0) * BH + j;
    g_h[dst]  = v;
    g_hh[dst] = __float2half_rn(v);
}

// ---------------- chunk loaders ---------------------------------------------
__device__ __forceinline__ void load_chunk_A(
    h16* slot, int kb, const h16* __restrict__ A, int tid)
{
    if (tid < 512) {
        int row = tid >> 3, c16 = tid & 7;   // 64 rows x 8 x 16B
        cp16(slot + row * SR + c16 * 8, A + (size_t)row * 1024 + kb + c16 * 8);
    }
}

// dst row-addressed at dst + row*SR (128 rows x 8 x 16B)
__device__ __forceinline__ void load_chunk_W_at(
    h16* dst, int kb, const h16* __restrict__ W, int tid)
{
#pragma unroll
    for (int i = tid; i < 1024; i += 512) {
        int row = i >> 3, c16 = i & 7;
        cp16(dst + row * SR + c16 * 8,
             W + (size_t)row * 1024 + kb + c16 * 8);
    }
}

// ---------------- persistent GRU kernel --------------------------------------
// grid (48, 3): l = blockIdx.y; q: p=q/24, g=(q%24)/8, ub=q%8. Each CTA loops
// t = 0..511 in its fixed role, synchronized by acquire/release flags.
// Single f16 product (f32 acc). W chunks 0..NPIN-1 pinned in smem (loaded once);
// remaining W chunks + all A chunks stream through the depth-3 cp.async ring.
__global__ __launch_bounds__(512) void gru_persistent_kernel(
    const float* __restrict__ bih, const float* __restrict__ bhh,
    float* __restrict__ out)
{
    const int l  = blockIdx.y;
    const int q  = blockIdx.x;
    const int p  = q / 24;
    const int g  = (q % 24) / 8;
    const int ub = q & 7;
    const int u0 = ub * 128;

    const int tid  = threadIdx.x;
    const int lane = tid & 31;
    const int wid  = tid >> 5;
    const int wm   = wid >> 2;
    const int wn   = wid & 3;

    extern __shared__ __align__(16) unsigned char smem_raw[];
    uint32_t dyn_u = (uint32_t)__cvta_generic_to_shared(smem_raw);
    uint32_t s0u   = (dyn_u + 1023u) & ~1023u;
    h16* sbase = (h16*)(smem_raw + (s0u - dyn_u));
    h16* pinW  = sbase + RING_HALFS;

    size_t wb = (size_t)(((l * 2 + p) * 3 + g) * 8 + ub) * WBLK;
    const h16* W = g_wB + wb;

    const int rowA  = wm * 16 + (lane & 15);
    const int ahalf = (lane >> 4) * 8;
    const int rowB  = (lane & 7) + ((lane & 16) ? 8 : 0);
    const int bhalf = (lane & 8) ? 8 : 0;

    const int lG = l * 3 * HID;
    const float* bihp = bih + lG;
    const float* bhhp = bhh + lG;
    const int sl    = p * 3 + g;
    const int start = sl * 1366;
    const int end   = (start + 1366 < 8192) ? start + 1366 : 8192;

    // ---- one-time: pin W chunks 0..NPIN-1 into smem ----
#pragma unroll
    for (int pc = 0; pc < NPIN; ++pc)
        load_chunk_W_at(pinW + pc * PINC_HALFS, pc * KCH, W, tid);
    asm volatile("cp.async.commit_group;" ::: "memory");
    asm volatile("cp.async.wait_group 0;" ::: "memory");
    __syncthreads();

    for (int t = 0; t < S_LEN; ++t) {
        const int par = t & 1;

        const h16* A;
        if (p == 0) {
            if (l == 0) A = g_x + (size_t)t * BH;
            else        A = g_hh + ((size_t)(l - 1) * 2 + (par ^ 1)) * BH; // h_{l-1}[t]
        } else {
            A = g_hh + ((size_t)l * 2 + par) * BH;                         // h_l[t-1]
        }

        float acc[4][4];
#pragma unroll
        for (int j = 0; j < 4; ++j)
#pragma unroll
            for (int c = 0; c < 4; ++c) acc[j][c] = 0.f;

        // ---- start-of-step flag spins ----
        if (tid == 0) {
            spin_ge(&g_lflag[l], 48 * t);                       // own layer t-1 done
            if (p == 0 && l > 0) spin_ge(&g_lflag[l - 1], 48 * (t + 1));
            if (l < LAYERS - 1 && t >= 1) spin_ge(&g_lflag[l + 1], 48 * (t - 1));
        }
        __syncthreads();
        // chunk 0: A only (W pinned) -> shortest possible first-chunk wait
        load_chunk_A(sbase, 0, A, tid);
        asm volatile("cp.async.commit_group;" ::: "memory");
        load_chunk_A(sbase + SLOT_HALFS, KCH, A, tid);          // chunk 1: A only
        asm volatile("cp.async.commit_group;" ::: "memory");

        // ---- main loop: 16 chunks, depth-3 ring ----
        for (int c = 0; c < CHUNKS; ++c) {
            asm volatile("cp.async.wait_group 1;" ::: "memory");
            __syncthreads();
            const int nc = c + DEPTH - 1;
            if (nc < CHUNKS) {
                h16* nslot = sbase + (size_t)(nc % DEPTH) * SLOT_HALFS;
                load_chunk_A(nslot, nc * KCH, A, tid);
                if (nc >= NPIN)
                    load_chunk_W_at(nslot + 64 * SR, nc * KCH, W, tid);
            }
            asm volatile("cp.async.commit_group;" ::: "memory");   // drain-safe

            const h16* slot = sbase + (size_t)(c % DEPTH) * SLOT_HALFS;
            const h16* wsrc = (c < NPIN) ? (pinW + (size_t)c * PINC_HALFS)
                                         : (slot + 64 * SR);
#pragma unroll
            for (int ks = 0; ks < 4; ++ks) {
                uint32_t a[4];
                ldsm4(a, slot + rowA * SR + ks * 16 + ahalf);
#pragma unroll
                for (int np = 0; np < 2; ++np) {
                    uint32_t wh[4];
                    int wr = wn * 32 + np * 16 + rowB;
                    ldsm4(wh, wsrc + wr * SR + ks * 16 + bhalf);
                    int f = np * 2;
                    mma_f32acc(acc[f],     a, wh[0], wh[1]);
                    mma_f32acc(acc[f + 1], a, wh[2], wh[3]);
                }
            }
        }
        asm volatile("cp.async.wait_group 0;" ::: "memory");

        // ---- store gate tile to global (parity-double-buffered) ----
        float* plane = g_gates + ((size_t)par * LAYERS * 6 + l * 6 + sl) * BH;
        {
            int gr = lane >> 2, t4 = lane & 3;
#pragma unroll
            for (int f = 0; f < 4; ++f) {
                int u = u0 + wn * 32 + f * 8 + t4 * 2;
                int r0 = wm * 16 + gr;
                *(float2*)(plane + (size_t)r0 * 1024 + u)       = make_float2(acc[f][0], acc[f][1]);
                *(float2*)(plane + (size_t)(r0 + 8) * 1024 + u) = make_float2(acc[f][2], acc[f][3]);
            }
        }

        // ---- group rendezvous: 6 CTAs of (l, ub) ----
        __syncthreads();
        if (tid == 0) {
            __threadfence();
            atomicAdd(&g_flag[l * 8 + ub], 1);
            spin_ge(&g_flag[l * 8 + ub], 6 * (t + 1));
        }
        __syncthreads();

        // ---- distributed pointwise GRU (slice sl of this ub's 8192 elems) ----
        const float* hsrc = g_h + ((size_t)l * 2 + par) * BH;
        float*       hdst = g_h + ((size_t)l * 2 + (par ^ 1)) * BH;
        h16* hhd = g_hh + ((size_t)l * 2 + (par ^ 1)) * BH;
        const float* GI = g_gates + ((size_t)par * LAYERS * 6 + l * 6) * BH;
        const float* GH = GI + 3 * (size_t)BH;

        for (int e = start + tid; e < end; e += 512) {
            int b  = e >> 7;
            int u  = u0 + (e & 127);
            size_t ix = (size_t)b * 1024 + u;
            float gi_r = __ldcg(GI + ix),                  gh_r = __ldcg(GH + ix);
            float gi_z = __ldcg(GI + BH + ix),             gh_z = __ldcg(GH + BH + ix);
            float gi_n = __ldcg(GI + 2 * (size_t)BH + ix), gh_n = __ldcg(GH + 2 * (size_t)BH + ix);
            float pr = gi_r + bihp[u]           + gh_r + bhhp[u];
            float pz = gi_z + bihp[HID + u]     + gh_z + bhhp[HID + u];
            float rg = 1.f / (1.f + __expf(-pr));
            float zg = 1.f / (1.f + __expf(-pz));
            float nn = tanhf(gi_n + bihp[2 * HID + u] + rg * (gh_n + bhhp[2 * HID + u]));
            float hold = hsrc[ix];
            float hn = (1.f - zg) * nn + zg * hold;
            hdst[ix] = hn;
            hhd[ix]  = __float2half_rn(hn);
            if (l == LAYERS - 1)
                out[(size_t)t * BH + ix] = hn;
        }

        // ---- release: this CTA completed step t ----
        __syncthreads();
        if (tid == 0) {
            __threadfence();
            atomicAdd(&g_lflag[l], 1);
        }
    }
}

// ---------------- launch -----------------------------------------------------
extern "C" void kernel_launch(void* const* d_in, const int* in_sizes, int n_in,
                              void* d_out, int out_size)
{
    const float* x   = (const float*)d_in[0];
    const float* h0  = (const float*)d_in[1];
    const float* wih = (const float*)d_in[2];
    const float* whh = (const float*)d_in[3];
    const float* bih = (const float*)d_in[4];
    const float* bhh = (const float*)d_in[5];
    float* out = (float*)d_out;

    cudaFuncSetAttribute(gru_persistent_kernel,
                         cudaFuncAttributeMaxDynamicSharedMemorySize, SMEM_REQ);

    {
        size_t n = (size_t)LAYERS * 3 * HID * HID;
        permute_weights_kernel<<<(unsigned)((n + 255) / 256), 256>>>(wih, whh);
    }
    {
        size_t n = (size_t)S_LEN * BH;
        cvt_x_kernel<<<(unsigned)((n + 255) / 256), 256>>>(x);
    }
    {
        size_t n = (size_t)LAYERS * BH;
        init_h_kernel<<<(unsigned)((n + 255) / 256), 256>>>(h0);  // + flag reset
    }
    gru_persistent_kernel<<<dim3(48, 3), 512, SMEM_REQ>>>(bih, bhh, out);
}